// round 14
// baseline (speedup 1.0000x reference)
#include <cuda_runtime.h>
#include <cuda_bf16.h>
#include <cstdint>
#include <cstddef>

// ---------------------------------------------------------------------------
// Problem dims (fixed)
// ---------------------------------------------------------------------------
#define BATCH   4
#define SEQ     2048
#define TOK     (BATCH * SEQ)      // 8192
#define DMODEL  384
#define INNER   768
#define STATE   16
#define KW      4
#define FFN     1024

// scan chunking
#define CH      16
#define CT      (SEQ / CH)         // 128

// padded x_proj width
#define NXPAD   128

// ---------------------------------------------------------------------------
// Scratch (device globals; no allocation allowed)
// ---------------------------------------------------------------------------
__device__ float g_h   [TOK * DMODEL];
__device__ float g_xz  [TOK * 2 * INNER];
__device__ float g_xc  [TOK * INNER];
__device__ float g_bc  [TOK * 2 * STATE];
__device__ float g_dl  [TOK * INNER];
__device__ float g_y   [TOK * INNER];
__device__ float g_o   [TOK * DMODEL];
__device__ float g_x2  [TOK * DMODEL];
__device__ float g_h2  [TOK * DMODEL];
__device__ float g_gate[TOK * FFN];
__device__ float g_hid [TOK * FFN];
__device__ float g_pa  [BATCH * CH * INNER * STATE];
__device__ float g_he  [BATCH * CH * INNER * STATE];
__device__ float g_hin [BATCH * CH * INNER * STATE];

// tf32-pre-rounded weights
__device__ float g_wip [DMODEL * 2 * INNER];
__device__ float g_wcv [KW * INNER * INNER];
__device__ float g_wxp [INNER * NXPAD];
__device__ float g_wdt [INNER * INNER];
__device__ float g_wop [INNER * DMODEL];
__device__ float g_wgt [DMODEL * FFN];
__device__ float g_wup [DMODEL * FFN];
__device__ float g_wdn [FFN * DMODEL];

// ---------------------------------------------------------------------------
// helpers
// ---------------------------------------------------------------------------
__device__ __forceinline__ float tf32r(float f)
{
    uint32_t u;
    asm("cvt.rna.tf32.f32 %0, %1;" : "=r"(u) : "f"(f));
    return __uint_as_float(u);
}

__device__ __forceinline__ void mma_tf32(float c[4], const uint32_t a[4],
                                         const uint32_t b[2])
{
    asm volatile(
        "mma.sync.aligned.m16n8k8.row.col.f32.tf32.tf32.f32 "
        "{%0,%1,%2,%3}, {%4,%5,%6,%7}, {%8,%9}, {%0,%1,%2,%3};\n"
        : "+f"(c[0]), "+f"(c[1]), "+f"(c[2]), "+f"(c[3])
        : "r"(a[0]), "r"(a[1]), "r"(a[2]), "r"(a[3]),
          "r"(b[0]), "r"(b[1]));
}

#define CP16(dst, src) \
    asm volatile("cp.async.cg.shared.global [%0], [%1], 16;\n" \
                 :: "r"(dst), "l"(src))
#define CP16Z(dst, src, sz) \
    asm volatile("cp.async.cg.shared.global [%0], [%1], 16, %2;\n" \
                 :: "r"(dst), "l"(src), "r"(sz))
#define CPCOMMIT() asm volatile("cp.async.commit_group;\n")
#define CPWAIT2()  asm volatile("cp.async.wait_group 2;\n")

// ---------------------------------------------------------------------------
// TF32 GEMM, cp.async 4-stage pipeline. All operands pre-rounded to tf32.
// C row-major with logical width Nc (stores guarded n < Nc).
// Requires M%128==0, N%128==0, K%16==0, K/16 >= 3.
// mode: 0 store, 1 silu(acc+bias), 2 acc+bias, 3 acc+res (NO rounding),
//       4 softplus(acc+bias), 5 silu(res)*acc.  Modes != 3 round to tf32.
// amode: 0 dense A [M,K]; 1 conv im2col view of xz (row stride 1536):
//        col k -> tap w=k/768, chan i=k%768; A[m][k] = xz[b, t-1+w][i],
//        zero-filled outside the sequence via cp.async src-size.
// ---------------------------------------------------------------------------
#define BM 128
#define BN 128
#define BKT 16
#define STG 4

__global__ __launch_bounds__(256, 2) void mma_gemm_kernel(
    const float* __restrict__ A, const float* __restrict__ B,
    float* __restrict__ C, int M, int N, int K, int Nc,
    int mode, const float* __restrict__ bias, const float* __restrict__ res,
    int amode)
{
    __shared__ float As[STG][128][20];
    __shared__ float Bs[STG][16][132];

    const int tid  = threadIdx.x;
    const int wid  = tid >> 5;
    const int lane = tid & 31;
    const int g    = lane >> 2;
    const int tig  = lane & 3;

    const int warpM = (wid & 3) * 32;
    const int warpN = (wid >> 2) * 64;

    const int m0 = blockIdx.y * BM;
    const int n0 = blockIdx.x * BN;

    const int ar  = tid >> 2;         // 0..63
    const int ac  = (tid & 3) * 4;    // 0,4,8,12
    const int br  = tid >> 5;         // 0..7
    const int bcn = (tid & 31) * 4;   // 0..124

    const int arow0 = m0 + ar;                 // rows arow0, arow0+64
    const float* a0p = A + (size_t)arow0 * K + ac;
    const float* a1p = A + (size_t)(arow0 + 64) * K + ac;
    const float* b0p = B + (size_t)br * N + n0 + bcn;
    const float* b1p = B + (size_t)(br + 8) * N + n0 + bcn;

    uint32_t sa0[STG], sa1[STG], sb0[STG], sb1[STG];
    #pragma unroll
    for (int s = 0; s < STG; s++) {
        sa0[s] = (uint32_t)__cvta_generic_to_shared(&As[s][ar][ac]);
        sa1[s] = (uint32_t)__cvta_generic_to_shared(&As[s][ar + 64][ac]);
        sb0[s] = (uint32_t)__cvta_generic_to_shared(&Bs[s][br][bcn]);
        sb1[s] = (uint32_t)__cvta_generic_to_shared(&Bs[s][br + 8][bcn]);
    }

    // issue one tile's cp.asyncs into stage s
    auto issue = [&](int tn, int s) {
        if (amode == 0) {
            CP16(sa0[s], a0p + tn * 16);
            CP16(sa1[s], a1p + tn * 16);
        } else {
            const int k = tn * 16 + ac;
            const int w = (k >= INNER) + (k >= 2 * INNER) + (k >= 3 * INNER);
            const int i = k - w * INNER;
            const int bbase = arow0 & ~(SEQ - 1);
            const int ts0 = (arow0 & (SEQ - 1)) - 1 + w;
            const int ts1 = ts0 + 64;
            const int cl0 = ts0 < 0 ? 0 : (ts0 > SEQ - 1 ? SEQ - 1 : ts0);
            const int cl1 = ts1 > SEQ - 1 ? SEQ - 1 : ts1;   // ts1 >= 63 >= 0
            const unsigned ok0 = ((unsigned)ts0 < SEQ) ? 16u : 0u;
            const unsigned ok1 = ((unsigned)ts1 < SEQ) ? 16u : 0u;
            CP16Z(sa0[s], A + (size_t)(bbase + cl0) * (2 * INNER) + i, ok0);
            CP16Z(sa1[s], A + (size_t)(bbase + cl1) * (2 * INNER) + i, ok1);
        }
        CP16(sb0[s], b0p + (size_t)(tn * 16) * N);
        CP16(sb1[s], b1p + (size_t)(tn * 16) * N);
    };

    float acc[2][8][4];
    #pragma unroll
    for (int mt = 0; mt < 2; mt++)
        #pragma unroll
        for (int nt = 0; nt < 8; nt++)
            #pragma unroll
            for (int r = 0; r < 4; r++) acc[mt][nt][r] = 0.f;

    const int ntiles = K / BKT;

    // prologue: tiles 0..2 -> stages 0..2
    #pragma unroll
    for (int s = 0; s < 3; s++) {
        issue(s, s);
        CPCOMMIT();
    }

    for (int t = 0; t < ntiles; t++) {
        CPWAIT2();
        __syncthreads();

        const int tn = t + 3;
        if (tn < ntiles)
            issue(tn, tn & 3);
        CPCOMMIT();

        const int st = t & 3;
        #pragma unroll
        for (int ks = 0; ks < BKT; ks += 8) {
            uint32_t afr[2][4];
            #pragma unroll
            for (int mt = 0; mt < 2; mt++) {
                const int mb = warpM + mt * 16 + g;
                afr[mt][0] = __float_as_uint(As[st][mb    ][ks + tig]);
                afr[mt][1] = __float_as_uint(As[st][mb + 8][ks + tig]);
                afr[mt][2] = __float_as_uint(As[st][mb    ][ks + tig + 4]);
                afr[mt][3] = __float_as_uint(As[st][mb + 8][ks + tig + 4]);
            }
            uint32_t bfr[8][2];
            #pragma unroll
            for (int nt = 0; nt < 8; nt++) {
                const int nb = warpN + nt * 8 + g;
                bfr[nt][0] = __float_as_uint(Bs[st][ks + tig    ][nb]);
                bfr[nt][1] = __float_as_uint(Bs[st][ks + tig + 4][nb]);
            }
            #pragma unroll
            for (int mt = 0; mt < 2; mt++)
                #pragma unroll
                for (int nt = 0; nt < 8; nt++)
                    mma_tf32(acc[mt][nt], afr[mt], bfr[nt]);
        }
    }

    // epilogue
    #pragma unroll
    for (int mt = 0; mt < 2; mt++) {
        #pragma unroll
        for (int nt = 0; nt < 8; nt++) {
            const int mA = m0 + warpM + mt * 16 + g;
            const int n  = n0 + warpN + nt * 8 + tig * 2;
            #pragma unroll
            for (int half = 0; half < 2; half++) {
                const int m = half ? (mA + 8) : mA;
                float v0 = half ? acc[mt][nt][2] : acc[mt][nt][0];
                float v1 = half ? acc[mt][nt][3] : acc[mt][nt][1];
                #pragma unroll
                for (int e = 0; e < 2; e++) {
                    const int nn = n + e;
                    float v = e ? v1 : v0;
                    if (nn >= Nc) continue;
                    if (mode == 1) {
                        v += bias[nn];
                        v = v / (1.f + __expf(-v));
                    } else if (mode == 2) {
                        v += bias[nn];
                    } else if (mode == 3) {
                        v += res[(size_t)m * Nc + nn];
                    } else if (mode == 4) {
                        v += bias[nn];
                        v = (v > 20.f) ? v : log1pf(__expf(v));
                    } else if (mode == 5) {
                        const float gv = res[(size_t)m * Nc + nn];
                        v *= gv / (1.f + __expf(-gv));
                    }
                    if (mode != 3) v = tf32r(v);
                    C[(size_t)m * Nc + nn] = v;
                }
            }
        }
    }
}

// ---------------------------------------------------------------------------
// Pre-round all weights into device globals (single launch).
// x_proj is padded 32 -> 128 columns with zeros.
// ---------------------------------------------------------------------------
#define NIP (DMODEL * 2 * INNER)
#define NCV (KW * INNER * INNER)
#define NXP (INNER * NXPAD)
#define NDT (INNER * INNER)
#define NOP (INNER * DMODEL)
#define NGT (DMODEL * FFN)
#define NTOTW (NIP + NCV + NXP + NDT + NOP + 3 * NGT)

__global__ void prep_weights_kernel(const float* __restrict__ ip,
                                    const float* __restrict__ cv,
                                    const float* __restrict__ xp,
                                    const float* __restrict__ dt,
                                    const float* __restrict__ op,
                                    const float* __restrict__ gt,
                                    const float* __restrict__ up,
                                    const float* __restrict__ dn)
{
    int i = blockIdx.x * blockDim.x + threadIdx.x;
    if (i >= NTOTW) return;
    if (i < NIP) { g_wip[i] = tf32r(ip[i]); return; }
    i -= NIP;
    if (i < NCV) { g_wcv[i] = tf32r(cv[i]); return; }
    i -= NCV;
    if (i < NXP) {
        const int k = i >> 7, n = i & (NXPAD - 1);
        g_wxp[i] = (n < 2 * STATE) ? tf32r(xp[k * 2 * STATE + n]) : 0.f;
        return;
    }
    i -= NXP;
    if (i < NDT) { g_wdt[i] = tf32r(dt[i]); return; }
    i -= NDT;
    if (i < NOP) { g_wop[i] = tf32r(op[i]); return; }
    i -= NOP;
    if (i < NGT) { g_wgt[i] = tf32r(gt[i]); return; }
    i -= NGT;
    if (i < NGT) { g_wup[i] = tf32r(up[i]); return; }
    i -= NGT;
    g_wdn[i] = tf32r(dn[i]);
}

// ---------------------------------------------------------------------------
// RMSNorm (warp per token) — output tf32-rounded
// ---------------------------------------------------------------------------
__global__ void rmsnorm_kernel(const float* __restrict__ x,
                               const float* __restrict__ w,
                               float* __restrict__ out)
{
    const int warp = (blockIdx.x * blockDim.x + threadIdx.x) >> 5;
    const int lane = threadIdx.x & 31;
    if (warp >= TOK) return;
    const float* row = x + (size_t)warp * DMODEL;
    float ss = 0.f;
    float v[12];
    #pragma unroll
    for (int c = 0; c < 12; c++) {
        v[c] = row[lane + c * 32];
        ss += v[c] * v[c];
    }
    #pragma unroll
    for (int o = 16; o; o >>= 1) ss += __shfl_xor_sync(0xffffffffu, ss, o);
    const float inv = rsqrtf(ss * (1.f / DMODEL) + 1e-6f);
    float* orow = out + (size_t)warp * DMODEL;
    #pragma unroll
    for (int c = 0; c < 12; c++) {
        const int i = lane + c * 32;
        orow[i] = tf32r(v[c] * inv * w[i]);
    }
}

// ---------------------------------------------------------------------------
// Chunked selective scan
// ---------------------------------------------------------------------------
__global__ void scan_chunk_kernel(const float* __restrict__ xc,
                                  const float* __restrict__ dsp_,
                                  const float* __restrict__ bc,
                                  const float* __restrict__ A_log,
                                  const float* __restrict__ Dp,
                                  float* __restrict__ yloc,
                                  float* __restrict__ pa,
                                  float* __restrict__ he)
{
    const int idx = blockIdx.x * blockDim.x + threadIdx.x;
    const int n = idx & 15;
    const int grp = idx >> 4;
    const int d = grp % INNER;
    const int bch = grp / INNER;
    const int c = bch & (CH - 1);
    const int b = bch >> 4;

    const float A = -__expf(A_log[d * STATE + n]);
    const float Dv = Dp[d];
    float S = 0.f, s = 0.f;

    size_t tok = (size_t)b * SEQ + (size_t)c * CT;

    float dsp = dsp_[tok * INNER + d];
    float xv  = xc[tok * INNER + d];
    float Bv  = bc[tok * 2 * STATE + n];
    float Cv  = bc[tok * 2 * STATE + STATE + n];

    for (int t = 0; t < CT; t++) {
        float dsp_nx = 0.f, x_nx = 0.f, b_nx = 0.f, c_nx = 0.f;
        if (t + 1 < CT) {
            const size_t tk = tok + 1;
            dsp_nx = dsp_[tk * INNER + d];
            x_nx   = xc[tk * INNER + d];
            b_nx   = bc[tk * 2 * STATE + n];
            c_nx   = bc[tk * 2 * STATE + STATE + n];
        }
        S += dsp;
        const float a = __expf(A * dsp);
        s = a * s + dsp * Bv * xv;
        float p = Cv * s;
        p += __shfl_xor_sync(0xffffffffu, p, 8);
        p += __shfl_xor_sync(0xffffffffu, p, 4);
        p += __shfl_xor_sync(0xffffffffu, p, 2);
        p += __shfl_xor_sync(0xffffffffu, p, 1);
        if (n == 0)
            yloc[tok * INNER + d] = p + Dv * xv;
        tok++;
        dsp = dsp_nx; xv = x_nx; Bv = b_nx; Cv = c_nx;
    }

    const size_t o = (size_t)grp * STATE + n;
    pa[o] = __expf(A * S);
    he[o] = s;
}

__global__ void scan_combine_kernel(const float* __restrict__ pa,
                                    const float* __restrict__ he,
                                    float* __restrict__ hin)
{
    const int idx = blockIdx.x * blockDim.x + threadIdx.x;
    if (idx >= BATCH * INNER * STATE) return;
    const int n = idx & 15;
    const int grp = idx >> 4;
    const int d = grp % INNER;
    const int b = grp / INNER;

    float h = 0.f;
    #pragma unroll
    for (int c = 0; c < CH; c++) {
        const size_t o = (((size_t)(b * CH + c) * INNER) + d) * STATE + n;
        hin[o] = h;
        h = pa[o] * h + he[o];
    }
}

__global__ void scan_fixup_kernel(const float* __restrict__ dsp_,
                                  const float* __restrict__ bc,
                                  const float* __restrict__ A_log,
                                  const float* __restrict__ hin,
                                  const float* __restrict__ yloc,
                                  const float* __restrict__ xz,
                                  float* __restrict__ y)
{
    const int idx = blockIdx.x * blockDim.x + threadIdx.x;
    const int n = idx & 15;
    const int grp = idx >> 4;
    const int d = grp % INNER;
    const int bch = grp / INNER;
    const int c = bch & (CH - 1);
    const int b = bch >> 4;

    const float A = -__expf(A_log[d * STATE + n]);
    const float h0 = hin[(size_t)grp * STATE + n];
    float S = 0.f;

    size_t tok = (size_t)b * SEQ + (size_t)c * CT;

    float dsp = dsp_[tok * INNER + d];
    float Cv  = bc[tok * 2 * STATE + STATE + n];

    for (int t = 0; t < CT; t++) {
        float dsp_nx = 0.f, c_nx = 0.f;
        if (t + 1 < CT) {
            const size_t tk = tok + 1;
            dsp_nx = dsp_[tk * INNER + d];
            c_nx   = bc[tk * 2 * STATE + STATE + n];
        }
        S += dsp;
        float p = Cv * __expf(A * S) * h0;
        p += __shfl_xor_sync(0xffffffffu, p, 8);
        p += __shfl_xor_sync(0xffffffffu, p, 4);
        p += __shfl_xor_sync(0xffffffffu, p, 2);
        p += __shfl_xor_sync(0xffffffffu, p, 1);
        if (n == 0) {
            const float zv = xz[tok * 2 * INNER + INNER + d];
            const float sz = zv / (1.f + __expf(-zv));
            y[tok * INNER + d] = tf32r((yloc[tok * INNER + d] + p) * sz);
        }
        tok++;
        dsp = dsp_nx; Cv = c_nx;
    }
}

// ---------------------------------------------------------------------------
// Fused: x2 = xres + LN(o); h2 = RMSNorm(x2)
// ---------------------------------------------------------------------------
__global__ void ln_residual_rms_kernel(const float* __restrict__ o_,
                                       const float* __restrict__ xres,
                                       const float* __restrict__ gamma,
                                       const float* __restrict__ beta,
                                       const float* __restrict__ rms_w,
                                       float* __restrict__ x2,
                                       float* __restrict__ h2)
{
    const int warp = (blockIdx.x * blockDim.x + threadIdx.x) >> 5;
    const int lane = threadIdx.x & 31;
    if (warp >= TOK) return;
    const size_t row = (size_t)warp * DMODEL;

    float o[12];
    float mu = 0.f;
    #pragma unroll
    for (int c = 0; c < 12; c++) {
        o[c] = o_[row + lane + c * 32];
        mu += o[c];
    }
    #pragma unroll
    for (int s = 16; s; s >>= 1) mu += __shfl_xor_sync(0xffffffffu, mu, s);
    mu *= (1.f / DMODEL);

    float var = 0.f;
    #pragma unroll
    for (int c = 0; c < 12; c++) {
        const float dd = o[c] - mu;
        var += dd * dd;
    }
    #pragma unroll
    for (int s = 16; s; s >>= 1) var += __shfl_xor_sync(0xffffffffu, var, s);
    var *= (1.f / DMODEL);
    const float inv = rsqrtf(var + 1e-5f);

    float r[12];
    float ss = 0.f;
    #pragma unroll
    for (int c = 0; c < 12; c++) {
        const int i = lane + c * 32;
        const float v = xres[row + i] + (o[c] - mu) * inv * gamma[i] + beta[i];
        r[c] = v;
        x2[row + i] = v;
        ss += v * v;
    }
    #pragma unroll
    for (int s = 16; s; s >>= 1) ss += __shfl_xor_sync(0xffffffffu, ss, s);
    const float rinv = rsqrtf(ss * (1.f / DMODEL) + 1e-6f);
    #pragma unroll
    for (int c = 0; c < 12; c++) {
        const int i = lane + c * 32;
        h2[row + i] = tf32r(r[c] * rinv * rms_w[i]);
    }
}

// ---------------------------------------------------------------------------
// launch
// ---------------------------------------------------------------------------
static inline float* sym(const void* symbol)
{
    void* p = nullptr;
    cudaGetSymbolAddress(&p, symbol);
    return (float*)p;
}

extern "C" void kernel_launch(void* const* d_in, const int* in_sizes, int n_in,
                              void* d_out, int out_size)
{
    const float* x        = (const float*)d_in[0];
    const float* rms1_w   = (const float*)d_in[1];
    const float* rms2_w   = (const float*)d_in[2];
    const float* in_proj  = (const float*)d_in[3];
    const float* conv_w   = (const float*)d_in[4];
    const float* conv_b   = (const float*)d_in[5];
    const float* x_proj   = (const float*)d_in[6];
    const float* dt_proj  = (const float*)d_in[7];
    const float* dt_b     = (const float*)d_in[8];
    const float* A_log    = (const float*)d_in[9];
    const float* D_param  = (const float*)d_in[10];
    const float* out_proj = (const float*)d_in[11];
    const float* ln_g     = (const float*)d_in[12];
    const float* ln_b     = (const float*)d_in[13];
    const float* gate_w   = (const float*)d_in[14];
    const float* up_w     = (const float*)d_in[15];
    const float* down_w   = (const float*)d_in[16];
    float* out = (float*)d_out;

    float* h    = sym(g_h);
    float* xz   = sym(g_xz);
    float* xc   = sym(g_xc);
    float* bcp  = sym(g_bc);
    float* dl   = sym(g_dl);
    float* y    = sym(g_y);
    float* o    = sym(g_o);
    float* x2   = sym(g_x2);
    float* h2   = sym(g_h2);
    float* gate = sym(g_gate);
    float* hid  = sym(g_hid);
    float* pa   = sym(g_pa);
    float* he   = sym(g_he);
    float* hin  = sym(g_hin);
    float* wip  = sym(g_wip);
    float* wcv  = sym(g_wcv);
    float* wxp  = sym(g_wxp);
    float* wdt  = sym(g_wdt);
    float* wop  = sym(g_wop);
    float* wgt  = sym(g_wgt);
    float* wup  = sym(g_wup);
    float* wdn  = sym(g_wdn);

    const dim3 tpb(256);

    // 0. pre-round (and pad) weights
    prep_weights_kernel<<<(NTOTW + 255) / 256, tpb>>>(
        in_proj, conv_w, x_proj, dt_proj, out_proj, gate_w, up_w, down_w);

    // 1. h = rmsnorm(x) (rounded)
    rmsnorm_kernel<<<TOK / 8, 256>>>(x, rms1_w, h);

    // 2. xz = h @ in_proj   N=1536 K=384
    mma_gemm_kernel<<<dim3(1536 / BN, TOK / BM), tpb>>>(
        h, wip, xz, TOK, 2 * INNER, DMODEL, 2 * INNER, 0, nullptr, nullptr, 0);

    // 3+4. xc = silu(conv(x_inner) + b) — im2col folded into cp.async A-path
    mma_gemm_kernel<<<dim3(INNER / BN, TOK / BM), tpb>>>(
        xz, wcv, xc, TOK, INNER, KW * INNER, INNER, 1, conv_b, nullptr, 1);

    // 5. bc = xc @ x_proj (padded N=128, logical 32)  K=768
    mma_gemm_kernel<<<dim3(NXPAD / BN, TOK / BM), tpb>>>(
        xc, wxp, bcp, TOK, NXPAD, INNER, 2 * STATE, 0, nullptr, nullptr, 0);

    // 6. dsp = softplus(xc @ dt_proj + dt_b)   N=768 K=768
    mma_gemm_kernel<<<dim3(INNER / BN, TOK / BM), tpb>>>(
        xc, wdt, dl, TOK, INNER, INNER, INNER, 4, dt_b, nullptr, 0);

    // 7. chunked scan + gating
    scan_chunk_kernel<<<(BATCH * CH * INNER * STATE) / 256, tpb>>>(
        xc, dl, bcp, A_log, D_param, y, pa, he);
    scan_combine_kernel<<<(BATCH * INNER * STATE + 255) / 256, tpb>>>(
        pa, he, hin);
    scan_fixup_kernel<<<(BATCH * CH * INNER * STATE) / 256, tpb>>>(
        dl, bcp, A_log, hin, y, xz, y);

    // 8. o = y @ out_proj   N=384 K=768
    mma_gemm_kernel<<<dim3(DMODEL / BN, TOK / BM), tpb>>>(
        y, wop, o, TOK, DMODEL, INNER, DMODEL, 0, nullptr, nullptr, 0);

    // 9. x2 = x + LN(o); h2 = RMSNorm(x2)
    ln_residual_rms_kernel<<<TOK / 8, 256>>>(o, x, ln_g, ln_b, rms2_w, x2, h2);

    // 10. gate = h2 @ gate_w   N=1024 K=384
    mma_gemm_kernel<<<dim3(FFN / BN, TOK / BM), tpb>>>(
        h2, wgt, gate, TOK, FFN, DMODEL, FFN, 0, nullptr, nullptr, 0);
    // 11. hid = silu(gate) * (h2 @ up_w)
    mma_gemm_kernel<<<dim3(FFN / BN, TOK / BM), tpb>>>(
        h2, wup, hid, TOK, FFN, DMODEL, FFN, 5, nullptr, gate, 0);

    // 12. out = x2 + hid @ down_w   N=384 K=1024  (exact, no rounding)
    mma_gemm_kernel<<<dim3(DMODEL / BN, TOK / BM), tpb>>>(
        hid, wdn, out, TOK, DMODEL, FFN, DMODEL, 3, nullptr, x2, 0);
}

// round 15
// speedup vs baseline: 1.0915x; 1.0915x over previous
#include <cuda_runtime.h>
#include <cuda_bf16.h>
#include <cstdint>
#include <cstddef>

// ---------------------------------------------------------------------------
// Problem dims (fixed)
// ---------------------------------------------------------------------------
#define BATCH   4
#define SEQ     2048
#define TOK     (BATCH * SEQ)      // 8192
#define DMODEL  384
#define INNER   768
#define STATE   16
#define KW      4
#define FFN     1024

// scan chunking
#define CH      16
#define CT      (SEQ / CH)         // 128

// padded x_proj width
#define NXPAD   128

// ---------------------------------------------------------------------------
// Scratch (device globals; no allocation allowed)
// ---------------------------------------------------------------------------
__device__ float g_h   [TOK * DMODEL];
__device__ float g_xz  [TOK * 2 * INNER];
__device__ float g_xc  [TOK * INNER];
__device__ float g_bc  [TOK * 2 * STATE];
__device__ float g_dl  [TOK * INNER];
__device__ float g_y   [TOK * INNER];
__device__ float g_o   [TOK * DMODEL];
__device__ float g_x2  [TOK * DMODEL];
__device__ float g_h2  [TOK * DMODEL];
__device__ float g_gate[TOK * FFN];
__device__ float g_hid [TOK * FFN];
__device__ float g_pa  [BATCH * CH * INNER * STATE];
__device__ float g_he  [BATCH * CH * INNER * STATE];
__device__ float g_hin [BATCH * CH * INNER * STATE];

// tf32-pre-rounded weights
__device__ float g_wip [DMODEL * 2 * INNER];
__device__ float g_wcv [KW * INNER * INNER];
__device__ float g_wxp [INNER * NXPAD];
__device__ float g_wdt [INNER * INNER];
__device__ float g_wop [INNER * DMODEL];
__device__ float g_wgt [DMODEL * FFN];
__device__ float g_wup [DMODEL * FFN];
__device__ float g_wdn [FFN * DMODEL];

// ---------------------------------------------------------------------------
// helpers
// ---------------------------------------------------------------------------
__device__ __forceinline__ float tf32r(float f)
{
    uint32_t u;
    asm("cvt.rna.tf32.f32 %0, %1;" : "=r"(u) : "f"(f));
    return __uint_as_float(u);
}

__device__ __forceinline__ void mma_tf32(float c[4], const uint32_t a[4],
                                         const uint32_t b[2])
{
    asm volatile(
        "mma.sync.aligned.m16n8k8.row.col.f32.tf32.tf32.f32 "
        "{%0,%1,%2,%3}, {%4,%5,%6,%7}, {%8,%9}, {%0,%1,%2,%3};\n"
        : "+f"(c[0]), "+f"(c[1]), "+f"(c[2]), "+f"(c[3])
        : "r"(a[0]), "r"(a[1]), "r"(a[2]), "r"(a[3]),
          "r"(b[0]), "r"(b[1]));
}

#define CP16(dst, src) \
    asm volatile("cp.async.cg.shared.global [%0], [%1], 16;\n" \
                 :: "r"(dst), "l"(src))
#define CP16Z(dst, src, sz) \
    asm volatile("cp.async.cg.shared.global [%0], [%1], 16, %2;\n" \
                 :: "r"(dst), "l"(src), "r"(sz))
#define CPCOMMIT() asm volatile("cp.async.commit_group;\n")
#define CPWAIT2()  asm volatile("cp.async.wait_group 2;\n")

// ---------------------------------------------------------------------------
// TF32 GEMM, cp.async 4-stage pipeline. All operands pre-rounded to tf32.
// Bs row stride 136 (136 mod 32 = 8) -> B-fragment LDS phase covers all 32
// banks (8*tig + g), conflict-free; stride 132 had systematic 2-way conflicts.
// C row-major with logical width Nc (stores guarded n < Nc).
// Requires M%128==0, N%128==0, K%16==0, K/16 >= 3.
// mode: 0 store, 1 silu(acc+bias), 2 acc+bias, 3 acc+res (NO rounding),
//       4 softplus(acc+bias), 5 silu(res)*acc.  Modes != 3 round to tf32.
// amode: 0 dense A [M,K]; 1 conv im2col view of xz (row stride 1536).
// ---------------------------------------------------------------------------
#define BM 128
#define BN 128
#define BKT 16
#define STG 4
#define BSTRIDE 136

__global__ __launch_bounds__(256, 2) void mma_gemm_kernel(
    const float* __restrict__ A, const float* __restrict__ B,
    float* __restrict__ C, int M, int N, int K, int Nc,
    int mode, const float* __restrict__ bias, const float* __restrict__ res,
    int amode)
{
    __shared__ float As[STG][128][20];
    __shared__ float Bs[STG][16][BSTRIDE];

    const int tid  = threadIdx.x;
    const int wid  = tid >> 5;
    const int lane = tid & 31;
    const int g    = lane >> 2;
    const int tig  = lane & 3;

    const int warpM = (wid & 3) * 32;
    const int warpN = (wid >> 2) * 64;

    const int m0 = blockIdx.y * BM;
    const int n0 = blockIdx.x * BN;

    const int ar  = tid >> 2;         // 0..63
    const int ac  = (tid & 3) * 4;    // 0,4,8,12
    const int br  = tid >> 5;         // 0..7
    const int bcn = (tid & 31) * 4;   // 0..124

    const int arow0 = m0 + ar;                 // rows arow0, arow0+64
    const float* a0p = A + (size_t)arow0 * K + ac;
    const float* a1p = A + (size_t)(arow0 + 64) * K + ac;
    const float* b0p = B + (size_t)br * N + n0 + bcn;
    const float* b1p = B + (size_t)(br + 8) * N + n0 + bcn;

    uint32_t sa0[STG], sa1[STG], sb0[STG], sb1[STG];
    #pragma unroll
    for (int s = 0; s < STG; s++) {
        sa0[s] = (uint32_t)__cvta_generic_to_shared(&As[s][ar][ac]);
        sa1[s] = (uint32_t)__cvta_generic_to_shared(&As[s][ar + 64][ac]);
        sb0[s] = (uint32_t)__cvta_generic_to_shared(&Bs[s][br][bcn]);
        sb1[s] = (uint32_t)__cvta_generic_to_shared(&Bs[s][br + 8][bcn]);
    }

    // issue one tile's cp.asyncs into stage s
    auto issue = [&](int tn, int s) {
        if (amode == 0) {
            CP16(sa0[s], a0p + tn * 16);
            CP16(sa1[s], a1p + tn * 16);
        } else {
            const int k = tn * 16 + ac;
            const int w = (k >= INNER) + (k >= 2 * INNER) + (k >= 3 * INNER);
            const int i = k - w * INNER;
            const int bbase = arow0 & ~(SEQ - 1);
            const int ts0 = (arow0 & (SEQ - 1)) - 1 + w;
            const int ts1 = ts0 + 64;
            const int cl0 = ts0 < 0 ? 0 : (ts0 > SEQ - 1 ? SEQ - 1 : ts0);
            const int cl1 = ts1 > SEQ - 1 ? SEQ - 1 : ts1;
            const unsigned ok0 = ((unsigned)ts0 < SEQ) ? 16u : 0u;
            const unsigned ok1 = ((unsigned)ts1 < SEQ) ? 16u : 0u;
            CP16Z(sa0[s], A + (size_t)(bbase + cl0) * (2 * INNER) + i, ok0);
            CP16Z(sa1[s], A + (size_t)(bbase + cl1) * (2 * INNER) + i, ok1);
        }
        CP16(sb0[s], b0p + (size_t)(tn * 16) * N);
        CP16(sb1[s], b1p + (size_t)(tn * 16) * N);
    };

    float acc[2][8][4];
    #pragma unroll
    for (int mt = 0; mt < 2; mt++)
        #pragma unroll
        for (int nt = 0; nt < 8; nt++)
            #pragma unroll
            for (int r = 0; r < 4; r++) acc[mt][nt][r] = 0.f;

    const int ntiles = K / BKT;

    // prologue: tiles 0..2 -> stages 0..2
    #pragma unroll
    for (int s = 0; s < 3; s++) {
        issue(s, s);
        CPCOMMIT();
    }

    for (int t = 0; t < ntiles; t++) {
        CPWAIT2();
        __syncthreads();

        const int tn = t + 3;
        if (tn < ntiles)
            issue(tn, tn & 3);
        CPCOMMIT();

        const int st = t & 3;
        #pragma unroll
        for (int ks = 0; ks < BKT; ks += 8) {
            uint32_t afr[2][4];
            #pragma unroll
            for (int mt = 0; mt < 2; mt++) {
                const int mb = warpM + mt * 16 + g;
                afr[mt][0] = __float_as_uint(As[st][mb    ][ks + tig]);
                afr[mt][1] = __float_as_uint(As[st][mb + 8][ks + tig]);
                afr[mt][2] = __float_as_uint(As[st][mb    ][ks + tig + 4]);
                afr[mt][3] = __float_as_uint(As[st][mb + 8][ks + tig + 4]);
            }
            uint32_t bfr[8][2];
            #pragma unroll
            for (int nt = 0; nt < 8; nt++) {
                const int nb = warpN + nt * 8 + g;
                bfr[nt][0] = __float_as_uint(Bs[st][ks + tig    ][nb]);
                bfr[nt][1] = __float_as_uint(Bs[st][ks + tig + 4][nb]);
            }
            #pragma unroll
            for (int mt = 0; mt < 2; mt++)
                #pragma unroll
                for (int nt = 0; nt < 8; nt++)
                    mma_tf32(acc[mt][nt], afr[mt], bfr[nt]);
        }
    }

    // epilogue
    #pragma unroll
    for (int mt = 0; mt < 2; mt++) {
        #pragma unroll
        for (int nt = 0; nt < 8; nt++) {
            const int mA = m0 + warpM + mt * 16 + g;
            const int n  = n0 + warpN + nt * 8 + tig * 2;
            #pragma unroll
            for (int half = 0; half < 2; half++) {
                const int m = half ? (mA + 8) : mA;
                float v0 = half ? acc[mt][nt][2] : acc[mt][nt][0];
                float v1 = half ? acc[mt][nt][3] : acc[mt][nt][1];
                #pragma unroll
                for (int e = 0; e < 2; e++) {
                    const int nn = n + e;
                    float v = e ? v1 : v0;
                    if (nn >= Nc) continue;
                    if (mode == 1) {
                        v += bias[nn];
                        v = v / (1.f + __expf(-v));
                    } else if (mode == 2) {
                        v += bias[nn];
                    } else if (mode == 3) {
                        v += res[(size_t)m * Nc + nn];
                    } else if (mode == 4) {
                        v += bias[nn];
                        v = (v > 20.f) ? v : log1pf(__expf(v));
                    } else if (mode == 5) {
                        const float gv = res[(size_t)m * Nc + nn];
                        v *= gv / (1.f + __expf(-gv));
                    }
                    if (mode != 3) v = tf32r(v);
                    C[(size_t)m * Nc + nn] = v;
                }
            }
        }
    }
}

// ---------------------------------------------------------------------------
// Pre-round all weights into device globals (single launch).
// x_proj is padded 32 -> 128 columns with zeros.
// ---------------------------------------------------------------------------
#define NIP (DMODEL * 2 * INNER)
#define NCV (KW * INNER * INNER)
#define NXP (INNER * NXPAD)
#define NDT (INNER * INNER)
#define NOP (INNER * DMODEL)
#define NGT (DMODEL * FFN)
#define NTOTW (NIP + NCV + NXP + NDT + NOP + 3 * NGT)

__global__ void prep_weights_kernel(const float* __restrict__ ip,
                                    const float* __restrict__ cv,
                                    const float* __restrict__ xp,
                                    const float* __restrict__ dt,
                                    const float* __restrict__ op,
                                    const float* __restrict__ gt,
                                    const float* __restrict__ up,
                                    const float* __restrict__ dn)
{
    int i = blockIdx.x * blockDim.x + threadIdx.x;
    if (i >= NTOTW) return;
    if (i < NIP) { g_wip[i] = tf32r(ip[i]); return; }
    i -= NIP;
    if (i < NCV) { g_wcv[i] = tf32r(cv[i]); return; }
    i -= NCV;
    if (i < NXP) {
        const int k = i >> 7, n = i & (NXPAD - 1);
        g_wxp[i] = (n < 2 * STATE) ? tf32r(xp[k * 2 * STATE + n]) : 0.f;
        return;
    }
    i -= NXP;
    if (i < NDT) { g_wdt[i] = tf32r(dt[i]); return; }
    i -= NDT;
    if (i < NOP) { g_wop[i] = tf32r(op[i]); return; }
    i -= NOP;
    if (i < NGT) { g_wgt[i] = tf32r(gt[i]); return; }
    i -= NGT;
    if (i < NGT) { g_wup[i] = tf32r(up[i]); return; }
    i -= NGT;
    g_wdn[i] = tf32r(dn[i]);
}

// ---------------------------------------------------------------------------
// RMSNorm (warp per token) — output tf32-rounded
// ---------------------------------------------------------------------------
__global__ void rmsnorm_kernel(const float* __restrict__ x,
                               const float* __restrict__ w,
                               float* __restrict__ out)
{
    const int warp = (blockIdx.x * blockDim.x + threadIdx.x) >> 5;
    const int lane = threadIdx.x & 31;
    if (warp >= TOK) return;
    const float* row = x + (size_t)warp * DMODEL;
    float ss = 0.f;
    float v[12];
    #pragma unroll
    for (int c = 0; c < 12; c++) {
        v[c] = row[lane + c * 32];
        ss += v[c] * v[c];
    }
    #pragma unroll
    for (int o = 16; o; o >>= 1) ss += __shfl_xor_sync(0xffffffffu, ss, o);
    const float inv = rsqrtf(ss * (1.f / DMODEL) + 1e-6f);
    float* orow = out + (size_t)warp * DMODEL;
    #pragma unroll
    for (int c = 0; c < 12; c++) {
        const int i = lane + c * 32;
        orow[i] = tf32r(v[c] * inv * w[i]);
    }
}

// ---------------------------------------------------------------------------
// Chunked selective scan
// ---------------------------------------------------------------------------
__global__ void scan_chunk_kernel(const float* __restrict__ xc,
                                  const float* __restrict__ dsp_,
                                  const float* __restrict__ bc,
                                  const float* __restrict__ A_log,
                                  const float* __restrict__ Dp,
                                  float* __restrict__ yloc,
                                  float* __restrict__ pa,
                                  float* __restrict__ he)
{
    const int idx = blockIdx.x * blockDim.x + threadIdx.x;
    const int n = idx & 15;
    const int grp = idx >> 4;
    const int d = grp % INNER;
    const int bch = grp / INNER;
    const int c = bch & (CH - 1);
    const int b = bch >> 4;

    const float A = -__expf(A_log[d * STATE + n]);
    const float Dv = Dp[d];
    float S = 0.f, s = 0.f;

    size_t tok = (size_t)b * SEQ + (size_t)c * CT;

    float dsp = dsp_[tok * INNER + d];
    float xv  = xc[tok * INNER + d];
    float Bv  = bc[tok * 2 * STATE + n];
    float Cv  = bc[tok * 2 * STATE + STATE + n];

    for (int t = 0; t < CT; t++) {
        float dsp_nx = 0.f, x_nx = 0.f, b_nx = 0.f, c_nx = 0.f;
        if (t + 1 < CT) {
            const size_t tk = tok + 1;
            dsp_nx = dsp_[tk * INNER + d];
            x_nx   = xc[tk * INNER + d];
            b_nx   = bc[tk * 2 * STATE + n];
            c_nx   = bc[tk * 2 * STATE + STATE + n];
        }
        S += dsp;
        const float a = __expf(A * dsp);
        s = a * s + dsp * Bv * xv;
        float p = Cv * s;
        p += __shfl_xor_sync(0xffffffffu, p, 8);
        p += __shfl_xor_sync(0xffffffffu, p, 4);
        p += __shfl_xor_sync(0xffffffffu, p, 2);
        p += __shfl_xor_sync(0xffffffffu, p, 1);
        if (n == 0)
            yloc[tok * INNER + d] = p + Dv * xv;
        tok++;
        dsp = dsp_nx; xv = x_nx; Bv = b_nx; Cv = c_nx;
    }

    const size_t o = (size_t)grp * STATE + n;
    pa[o] = __expf(A * S);
    he[o] = s;
}

__global__ void scan_combine_kernel(const float* __restrict__ pa,
                                    const float* __restrict__ he,
                                    float* __restrict__ hin)
{
    const int idx = blockIdx.x * blockDim.x + threadIdx.x;
    if (idx >= BATCH * INNER * STATE) return;
    const int n = idx & 15;
    const int grp = idx >> 4;
    const int d = grp % INNER;
    const int b = grp / INNER;

    float h = 0.f;
    #pragma unroll
    for (int c = 0; c < CH; c++) {
        const size_t o = (((size_t)(b * CH + c) * INNER) + d) * STATE + n;
        hin[o] = h;
        h = pa[o] * h + he[o];
    }
}

__global__ void scan_fixup_kernel(const float* __restrict__ dsp_,
                                  const float* __restrict__ bc,
                                  const float* __restrict__ A_log,
                                  const float* __restrict__ hin,
                                  const float* __restrict__ yloc,
                                  const float* __restrict__ xz,
                                  float* __restrict__ y)
{
    const int idx = blockIdx.x * blockDim.x + threadIdx.x;
    const int n = idx & 15;
    const int grp = idx >> 4;
    const int d = grp % INNER;
    const int bch = grp / INNER;
    const int c = bch & (CH - 1);
    const int b = bch >> 4;

    const float A = -__expf(A_log[d * STATE + n]);
    const float h0 = hin[(size_t)grp * STATE + n];
    float S = 0.f;

    size_t tok = (size_t)b * SEQ + (size_t)c * CT;

    float dsp = dsp_[tok * INNER + d];
    float Cv  = bc[tok * 2 * STATE + STATE + n];

    for (int t = 0; t < CT; t++) {
        float dsp_nx = 0.f, c_nx = 0.f;
        if (t + 1 < CT) {
            const size_t tk = tok + 1;
            dsp_nx = dsp_[tk * INNER + d];
            c_nx   = bc[tk * 2 * STATE + STATE + n];
        }
        S += dsp;
        float p = Cv * __expf(A * S) * h0;
        p += __shfl_xor_sync(0xffffffffu, p, 8);
        p += __shfl_xor_sync(0xffffffffu, p, 4);
        p += __shfl_xor_sync(0xffffffffu, p, 2);
        p += __shfl_xor_sync(0xffffffffu, p, 1);
        if (n == 0) {
            const float zv = xz[tok * 2 * INNER + INNER + d];
            const float sz = zv / (1.f + __expf(-zv));
            y[tok * INNER + d] = tf32r((yloc[tok * INNER + d] + p) * sz);
        }
        tok++;
        dsp = dsp_nx; Cv = c_nx;
    }
}

// ---------------------------------------------------------------------------
// Fused: x2 = xres + LN(o); h2 = RMSNorm(x2)
// ---------------------------------------------------------------------------
__global__ void ln_residual_rms_kernel(const float* __restrict__ o_,
                                       const float* __restrict__ xres,
                                       const float* __restrict__ gamma,
                                       const float* __restrict__ beta,
                                       const float* __restrict__ rms_w,
                                       float* __restrict__ x2,
                                       float* __restrict__ h2)
{
    const int warp = (blockIdx.x * blockDim.x + threadIdx.x) >> 5;
    const int lane = threadIdx.x & 31;
    if (warp >= TOK) return;
    const size_t row = (size_t)warp * DMODEL;

    float o[12];
    float mu = 0.f;
    #pragma unroll
    for (int c = 0; c < 12; c++) {
        o[c] = o_[row + lane + c * 32];
        mu += o[c];
    }
    #pragma unroll
    for (int s = 16; s; s >>= 1) mu += __shfl_xor_sync(0xffffffffu, mu, s);
    mu *= (1.f / DMODEL);

    float var = 0.f;
    #pragma unroll
    for (int c = 0; c < 12; c++) {
        const float dd = o[c] - mu;
        var += dd * dd;
    }
    #pragma unroll
    for (int s = 16; s; s >>= 1) var += __shfl_xor_sync(0xffffffffu, var, s);
    var *= (1.f / DMODEL);
    const float inv = rsqrtf(var + 1e-5f);

    float r[12];
    float ss = 0.f;
    #pragma unroll
    for (int c = 0; c < 12; c++) {
        const int i = lane + c * 32;
        const float v = xres[row + i] + (o[c] - mu) * inv * gamma[i] + beta[i];
        r[c] = v;
        x2[row + i] = v;
        ss += v * v;
    }
    #pragma unroll
    for (int s = 16; s; s >>= 1) ss += __shfl_xor_sync(0xffffffffu, ss, s);
    const float rinv = rsqrtf(ss * (1.f / DMODEL) + 1e-6f);
    #pragma unroll
    for (int c = 0; c < 12; c++) {
        const int i = lane + c * 32;
        h2[row + i] = tf32r(r[c] * rinv * rms_w[i]);
    }
}

// ---------------------------------------------------------------------------
// launch
// ---------------------------------------------------------------------------
static inline float* sym(const void* symbol)
{
    void* p = nullptr;
    cudaGetSymbolAddress(&p, symbol);
    return (float*)p;
}

extern "C" void kernel_launch(void* const* d_in, const int* in_sizes, int n_in,
                              void* d_out, int out_size)
{
    const float* x        = (const float*)d_in[0];
    const float* rms1_w   = (const float*)d_in[1];
    const float* rms2_w   = (const float*)d_in[2];
    const float* in_proj  = (const float*)d_in[3];
    const float* conv_w   = (const float*)d_in[4];
    const float* conv_b   = (const float*)d_in[5];
    const float* x_proj   = (const float*)d_in[6];
    const float* dt_proj  = (const float*)d_in[7];
    const float* dt_b     = (const float*)d_in[8];
    const float* A_log    = (const float*)d_in[9];
    const float* D_param  = (const float*)d_in[10];
    const float* out_proj = (const float*)d_in[11];
    const float* ln_g     = (const float*)d_in[12];
    const float* ln_b     = (const float*)d_in[13];
    const float* gate_w   = (const float*)d_in[14];
    const float* up_w     = (const float*)d_in[15];
    const float* down_w   = (const float*)d_in[16];
    float* out = (float*)d_out;

    float* h    = sym(g_h);
    float* xz   = sym(g_xz);
    float* xc   = sym(g_xc);
    float* bcp  = sym(g_bc);
    float* dl   = sym(g_dl);
    float* y    = sym(g_y);
    float* o    = sym(g_o);
    float* x2   = sym(g_x2);
    float* h2   = sym(g_h2);
    float* gate = sym(g_gate);
    float* hid  = sym(g_hid);
    float* pa   = sym(g_pa);
    float* he   = sym(g_he);
    float* hin  = sym(g_hin);
    float* wip  = sym(g_wip);
    float* wcv  = sym(g_wcv);
    float* wxp  = sym(g_wxp);
    float* wdt  = sym(g_wdt);
    float* wop  = sym(g_wop);
    float* wgt  = sym(g_wgt);
    float* wup  = sym(g_wup);
    float* wdn  = sym(g_wdn);

    const dim3 tpb(256);

    // 0. pre-round (and pad) weights
    prep_weights_kernel<<<(NTOTW + 255) / 256, tpb>>>(
        in_proj, conv_w, x_proj, dt_proj, out_proj, gate_w, up_w, down_w);

    // 1. h = rmsnorm(x) (rounded)
    rmsnorm_kernel<<<TOK / 8, 256>>>(x, rms1_w, h);

    // 2. xz = h @ in_proj   N=1536 K=384
    mma_gemm_kernel<<<dim3(1536 / BN, TOK / BM), tpb>>>(
        h, wip, xz, TOK, 2 * INNER, DMODEL, 2 * INNER, 0, nullptr, nullptr, 0);

    // 3+4. xc = silu(conv(x_inner) + b) — im2col folded into cp.async A-path
    mma_gemm_kernel<<<dim3(INNER / BN, TOK / BM), tpb>>>(
        xz, wcv, xc, TOK, INNER, KW * INNER, INNER, 1, conv_b, nullptr, 1);

    // 5. bc = xc @ x_proj (padded N=128, logical 32)  K=768
    mma_gemm_kernel<<<dim3(NXPAD / BN, TOK / BM), tpb>>>(
        xc, wxp, bcp, TOK, NXPAD, INNER, 2 * STATE, 0, nullptr, nullptr, 0);

    // 6. dsp = softplus(xc @ dt_proj + dt_b)   N=768 K=768
    mma_gemm_kernel<<<dim3(INNER / BN, TOK / BM), tpb>>>(
        xc, wdt, dl, TOK, INNER, INNER, INNER, 4, dt_b, nullptr, 0);

    // 7. chunked scan + gating
    scan_chunk_kernel<<<(BATCH * CH * INNER * STATE) / 256, tpb>>>(
        xc, dl, bcp, A_log, D_param, y, pa, he);
    scan_combine_kernel<<<(BATCH * INNER * STATE + 255) / 256, tpb>>>(
        pa, he, hin);
    scan_fixup_kernel<<<(BATCH * CH * INNER * STATE) / 256, tpb>>>(
        dl, bcp, A_log, hin, y, xz, y);

    // 8. o = y @ out_proj   N=384 K=768
    mma_gemm_kernel<<<dim3(DMODEL / BN, TOK / BM), tpb>>>(
        y, wop, o, TOK, DMODEL, INNER, DMODEL, 0, nullptr, nullptr, 0);

    // 9. x2 = x + LN(o); h2 = RMSNorm(x2)
    ln_residual_rms_kernel<<<TOK / 8, 256>>>(o, x, ln_g, ln_b, rms2_w, x2, h2);

    // 10. gate = h2 @ gate_w   N=1024 K=384
    mma_gemm_kernel<<<dim3(FFN / BN, TOK / BM), tpb>>>(
        h2, wgt, gate, TOK, FFN, DMODEL, FFN, 0, nullptr, nullptr, 0);
    // 11. hid = silu(gate) * (h2 @ up_w)
    mma_gemm_kernel<<<dim3(FFN / BN, TOK / BM), tpb>>>(
        h2, wup, hid, TOK, FFN, DMODEL, FFN, 5, nullptr, gate, 0);

    // 12. out = x2 + hid @ down_w   N=384 K=1024  (exact, no rounding)
    mma_gemm_kernel<<<dim3(DMODEL / BN, TOK / BM), tpb>>>(
        hid, wdn, out, TOK, DMODEL, FFN, DMODEL, 3, nullptr, x2, 0);
}

// round 16
// speedup vs baseline: 1.1176x; 1.0239x over previous
#include <cuda_runtime.h>
#include <cuda_bf16.h>
#include <cstdint>
#include <cstddef>

// ---------------------------------------------------------------------------
// Problem dims (fixed)
// ---------------------------------------------------------------------------
#define BATCH   4
#define SEQ     2048
#define TOK     (BATCH * SEQ)      // 8192
#define DMODEL  384
#define INNER   768
#define STATE   16
#define KW      4
#define FFN     1024

// scan chunking
#define CH      16
#define CT      (SEQ / CH)         // 128

// padded x_proj width
#define NXPAD   128

// ---------------------------------------------------------------------------
// Scratch (device globals; no allocation allowed)
// ---------------------------------------------------------------------------
__device__ float g_h   [TOK * DMODEL];
__device__ float g_xz  [TOK * 2 * INNER];
__device__ float g_xc  [TOK * INNER];
__device__ float g_bc  [TOK * 2 * STATE];
__device__ float g_dl  [TOK * INNER];
__device__ float g_y   [TOK * INNER];
__device__ float g_o   [TOK * DMODEL];
__device__ float g_x2  [TOK * DMODEL];
__device__ float g_h2  [TOK * DMODEL];
__device__ float g_gate[TOK * FFN];
__device__ float g_hid [TOK * FFN];
__device__ float g_pa  [BATCH * CH * INNER * STATE];
__device__ float g_he  [BATCH * CH * INNER * STATE];
__device__ float g_hin [BATCH * CH * INNER * STATE];

// tf32-pre-rounded weights
__device__ float g_wip [DMODEL * 2 * INNER];
__device__ float g_wcv [KW * INNER * INNER];
__device__ float g_wxp [INNER * NXPAD];
__device__ float g_wdt [INNER * INNER];
__device__ float g_wop [INNER * DMODEL];
__device__ float g_wgt [DMODEL * FFN];
__device__ float g_wup [DMODEL * FFN];
__device__ float g_wdn [FFN * DMODEL];

// ---------------------------------------------------------------------------
// helpers
// ---------------------------------------------------------------------------
__device__ __forceinline__ float tf32r(float f)
{
    uint32_t u;
    asm("cvt.rna.tf32.f32 %0, %1;" : "=r"(u) : "f"(f));
    return __uint_as_float(u);
}

__device__ __forceinline__ void mma_tf32(float c[4], const uint32_t a[4],
                                         const uint32_t b[2])
{
    asm volatile(
        "mma.sync.aligned.m16n8k8.row.col.f32.tf32.tf32.f32 "
        "{%0,%1,%2,%3}, {%4,%5,%6,%7}, {%8,%9}, {%0,%1,%2,%3};\n"
        : "+f"(c[0]), "+f"(c[1]), "+f"(c[2]), "+f"(c[3])
        : "r"(a[0]), "r"(a[1]), "r"(a[2]), "r"(a[3]),
          "r"(b[0]), "r"(b[1]));
}

#define CP16(dst, src) \
    asm volatile("cp.async.cg.shared.global [%0], [%1], 16;\n" \
                 :: "r"(dst), "l"(src))
#define CP16Z(dst, src, sz) \
    asm volatile("cp.async.cg.shared.global [%0], [%1], 16, %2;\n" \
                 :: "r"(dst), "l"(src), "r"(sz))
#define CPCOMMIT() asm volatile("cp.async.commit_group;\n")
#define CPWAIT2()  asm volatile("cp.async.wait_group 2;\n")

// ---------------------------------------------------------------------------
// TF32 GEMM, cp.async 4-stage pipeline. All operands pre-rounded to tf32.
// Bs row stride 136 (mod 32 = 8) -> conflict-free B-fragment LDS.
// mode: 0 store, 1 silu(acc+bias), 2 acc+bias, 3 acc+res (NO rounding),
//       4 softplus(acc+bias), 5 silu(res)*acc.  Modes != 3 round to tf32.
// amode: 0 dense A [M,K]; 1 conv im2col view of xz (row stride 1536).
// ---------------------------------------------------------------------------
#define BM 128
#define BN 128
#define BKT 16
#define STG 4
#define BSTRIDE 136

__global__ __launch_bounds__(256, 2) void mma_gemm_kernel(
    const float* __restrict__ A, const float* __restrict__ B,
    float* __restrict__ C, int M, int N, int K, int Nc,
    int mode, const float* __restrict__ bias, const float* __restrict__ res,
    int amode)
{
    __shared__ float As[STG][128][20];
    __shared__ float Bs[STG][16][BSTRIDE];

    const int tid  = threadIdx.x;
    const int wid  = tid >> 5;
    const int lane = tid & 31;
    const int g    = lane >> 2;
    const int tig  = lane & 3;

    const int warpM = (wid & 3) * 32;
    const int warpN = (wid >> 2) * 64;

    const int m0 = blockIdx.y * BM;
    const int n0 = blockIdx.x * BN;

    const int ar  = tid >> 2;         // 0..63
    const int ac  = (tid & 3) * 4;    // 0,4,8,12
    const int br  = tid >> 5;         // 0..7
    const int bcn = (tid & 31) * 4;   // 0..124

    const int arow0 = m0 + ar;                 // rows arow0, arow0+64
    const float* a0p = A + (size_t)arow0 * K + ac;
    const float* a1p = A + (size_t)(arow0 + 64) * K + ac;
    const float* b0p = B + (size_t)br * N + n0 + bcn;
    const float* b1p = B + (size_t)(br + 8) * N + n0 + bcn;

    uint32_t sa0[STG], sa1[STG], sb0[STG], sb1[STG];
    #pragma unroll
    for (int s = 0; s < STG; s++) {
        sa0[s] = (uint32_t)__cvta_generic_to_shared(&As[s][ar][ac]);
        sa1[s] = (uint32_t)__cvta_generic_to_shared(&As[s][ar + 64][ac]);
        sb0[s] = (uint32_t)__cvta_generic_to_shared(&Bs[s][br][bcn]);
        sb1[s] = (uint32_t)__cvta_generic_to_shared(&Bs[s][br + 8][bcn]);
    }

    // issue one tile's cp.asyncs into stage s
    auto issue = [&](int tn, int s) {
        if (amode == 0) {
            CP16(sa0[s], a0p + tn * 16);
            CP16(sa1[s], a1p + tn * 16);
        } else {
            const int k = tn * 16 + ac;
            const int w = (k >= INNER) + (k >= 2 * INNER) + (k >= 3 * INNER);
            const int i = k - w * INNER;
            const int bbase = arow0 & ~(SEQ - 1);
            const int ts0 = (arow0 & (SEQ - 1)) - 1 + w;
            const int ts1 = ts0 + 64;
            const int cl0 = ts0 < 0 ? 0 : (ts0 > SEQ - 1 ? SEQ - 1 : ts0);
            const int cl1 = ts1 > SEQ - 1 ? SEQ - 1 : ts1;
            const unsigned ok0 = ((unsigned)ts0 < SEQ) ? 16u : 0u;
            const unsigned ok1 = ((unsigned)ts1 < SEQ) ? 16u : 0u;
            CP16Z(sa0[s], A + (size_t)(bbase + cl0) * (2 * INNER) + i, ok0);
            CP16Z(sa1[s], A + (size_t)(bbase + cl1) * (2 * INNER) + i, ok1);
        }
        CP16(sb0[s], b0p + (size_t)(tn * 16) * N);
        CP16(sb1[s], b1p + (size_t)(tn * 16) * N);
    };

    float acc[2][8][4];
    #pragma unroll
    for (int mt = 0; mt < 2; mt++)
        #pragma unroll
        for (int nt = 0; nt < 8; nt++)
            #pragma unroll
            for (int r = 0; r < 4; r++) acc[mt][nt][r] = 0.f;

    const int ntiles = K / BKT;

    // prologue: tiles 0..2 -> stages 0..2
    #pragma unroll
    for (int s = 0; s < 3; s++) {
        issue(s, s);
        CPCOMMIT();
    }

    for (int t = 0; t < ntiles; t++) {
        CPWAIT2();
        __syncthreads();

        const int tn = t + 3;
        if (tn < ntiles)
            issue(tn, tn & 3);
        CPCOMMIT();

        const int st = t & 3;
        #pragma unroll
        for (int ks = 0; ks < BKT; ks += 8) {
            uint32_t afr[2][4];
            #pragma unroll
            for (int mt = 0; mt < 2; mt++) {
                const int mb = warpM + mt * 16 + g;
                afr[mt][0] = __float_as_uint(As[st][mb    ][ks + tig]);
                afr[mt][1] = __float_as_uint(As[st][mb + 8][ks + tig]);
                afr[mt][2] = __float_as_uint(As[st][mb    ][ks + tig + 4]);
                afr[mt][3] = __float_as_uint(As[st][mb + 8][ks + tig + 4]);
            }
            uint32_t bfr[8][2];
            #pragma unroll
            for (int nt = 0; nt < 8; nt++) {
                const int nb = warpN + nt * 8 + g;
                bfr[nt][0] = __float_as_uint(Bs[st][ks + tig    ][nb]);
                bfr[nt][1] = __float_as_uint(Bs[st][ks + tig + 4][nb]);
            }
            #pragma unroll
            for (int mt = 0; mt < 2; mt++)
                #pragma unroll
                for (int nt = 0; nt < 8; nt++)
                    mma_tf32(acc[mt][nt], afr[mt], bfr[nt]);
        }
    }

    // epilogue
    #pragma unroll
    for (int mt = 0; mt < 2; mt++) {
        #pragma unroll
        for (int nt = 0; nt < 8; nt++) {
            const int mA = m0 + warpM + mt * 16 + g;
            const int n  = n0 + warpN + nt * 8 + tig * 2;
            #pragma unroll
            for (int half = 0; half < 2; half++) {
                const int m = half ? (mA + 8) : mA;
                float v0 = half ? acc[mt][nt][2] : acc[mt][nt][0];
                float v1 = half ? acc[mt][nt][3] : acc[mt][nt][1];
                #pragma unroll
                for (int e = 0; e < 2; e++) {
                    const int nn = n + e;
                    float v = e ? v1 : v0;
                    if (nn >= Nc) continue;
                    if (mode == 1) {
                        v += bias[nn];
                        v = v / (1.f + __expf(-v));
                    } else if (mode == 2) {
                        v += bias[nn];
                    } else if (mode == 3) {
                        v += res[(size_t)m * Nc + nn];
                    } else if (mode == 4) {
                        v += bias[nn];
                        v = (v > 20.f) ? v : log1pf(__expf(v));
                    } else if (mode == 5) {
                        const float gv = res[(size_t)m * Nc + nn];
                        v *= gv / (1.f + __expf(-gv));
                    }
                    if (mode != 3) v = tf32r(v);
                    C[(size_t)m * Nc + nn] = v;
                }
            }
        }
    }
}

// ---------------------------------------------------------------------------
// Pre-round all weights into device globals (single launch).
// x_proj is padded 32 -> 128 columns with zeros.
// ---------------------------------------------------------------------------
#define NIP (DMODEL * 2 * INNER)
#define NCV (KW * INNER * INNER)
#define NXP (INNER * NXPAD)
#define NDT (INNER * INNER)
#define NOP (INNER * DMODEL)
#define NGT (DMODEL * FFN)
#define NTOTW (NIP + NCV + NXP + NDT + NOP + 3 * NGT)

__global__ void prep_weights_kernel(const float* __restrict__ ip,
                                    const float* __restrict__ cv,
                                    const float* __restrict__ xp,
                                    const float* __restrict__ dt,
                                    const float* __restrict__ op,
                                    const float* __restrict__ gt,
                                    const float* __restrict__ up,
                                    const float* __restrict__ dn)
{
    int i = blockIdx.x * blockDim.x + threadIdx.x;
    if (i >= NTOTW) return;
    if (i < NIP) { g_wip[i] = tf32r(ip[i]); return; }
    i -= NIP;
    if (i < NCV) { g_wcv[i] = tf32r(cv[i]); return; }
    i -= NCV;
    if (i < NXP) {
        const int k = i >> 7, n = i & (NXPAD - 1);
        g_wxp[i] = (n < 2 * STATE) ? tf32r(xp[k * 2 * STATE + n]) : 0.f;
        return;
    }
    i -= NXP;
    if (i < NDT) { g_wdt[i] = tf32r(dt[i]); return; }
    i -= NDT;
    if (i < NOP) { g_wop[i] = tf32r(op[i]); return; }
    i -= NOP;
    if (i < NGT) { g_wgt[i] = tf32r(gt[i]); return; }
    i -= NGT;
    if (i < NGT) { g_wup[i] = tf32r(up[i]); return; }
    i -= NGT;
    g_wdn[i] = tf32r(dn[i]);
}

// ---------------------------------------------------------------------------
// RMSNorm (warp per token) — output tf32-rounded
// ---------------------------------------------------------------------------
__global__ void rmsnorm_kernel(const float* __restrict__ x,
                               const float* __restrict__ w,
                               float* __restrict__ out)
{
    const int warp = (blockIdx.x * blockDim.x + threadIdx.x) >> 5;
    const int lane = threadIdx.x & 31;
    if (warp >= TOK) return;
    const float* row = x + (size_t)warp * DMODEL;
    float ss = 0.f;
    float v[12];
    #pragma unroll
    for (int c = 0; c < 12; c++) {
        v[c] = row[lane + c * 32];
        ss += v[c] * v[c];
    }
    #pragma unroll
    for (int o = 16; o; o >>= 1) ss += __shfl_xor_sync(0xffffffffu, ss, o);
    const float inv = rsqrtf(ss * (1.f / DMODEL) + 1e-6f);
    float* orow = out + (size_t)warp * DMODEL;
    #pragma unroll
    for (int c = 0; c < 12; c++) {
        const int i = lane + c * 32;
        orow[i] = tf32r(v[c] * inv * w[i]);
    }
}

// ---------------------------------------------------------------------------
// Chunked selective scan
// ---------------------------------------------------------------------------
__global__ void scan_chunk_kernel(const float* __restrict__ xc,
                                  const float* __restrict__ dsp_,
                                  const float* __restrict__ bc,
                                  const float* __restrict__ A_log,
                                  const float* __restrict__ Dp,
                                  float* __restrict__ yloc,
                                  float* __restrict__ pa,
                                  float* __restrict__ he)
{
    const int idx = blockIdx.x * blockDim.x + threadIdx.x;
    const int n = idx & 15;
    const int grp = idx >> 4;
    const int d = grp % INNER;
    const int bch = grp / INNER;
    const int c = bch & (CH - 1);
    const int b = bch >> 4;

    const float A = -__expf(A_log[d * STATE + n]);
    const float Dv = Dp[d];
    float S = 0.f, s = 0.f;

    size_t tok = (size_t)b * SEQ + (size_t)c * CT;

    float dsp = dsp_[tok * INNER + d];
    float xv  = xc[tok * INNER + d];
    float Bv  = bc[tok * 2 * STATE + n];
    float Cv  = bc[tok * 2 * STATE + STATE + n];

    for (int t = 0; t < CT; t++) {
        float dsp_nx = 0.f, x_nx = 0.f, b_nx = 0.f, c_nx = 0.f;
        if (t + 1 < CT) {
            const size_t tk = tok + 1;
            dsp_nx = dsp_[tk * INNER + d];
            x_nx   = xc[tk * INNER + d];
            b_nx   = bc[tk * 2 * STATE + n];
            c_nx   = bc[tk * 2 * STATE + STATE + n];
        }
        S += dsp;
        const float a = __expf(A * dsp);
        s = a * s + dsp * Bv * xv;
        float p = Cv * s;
        p += __shfl_xor_sync(0xffffffffu, p, 8);
        p += __shfl_xor_sync(0xffffffffu, p, 4);
        p += __shfl_xor_sync(0xffffffffu, p, 2);
        p += __shfl_xor_sync(0xffffffffu, p, 1);
        if (n == 0)
            yloc[tok * INNER + d] = p + Dv * xv;
        tok++;
        dsp = dsp_nx; xv = x_nx; Bv = b_nx; Cv = c_nx;
    }

    const size_t o = (size_t)grp * STATE + n;
    pa[o] = __expf(A * S);
    he[o] = s;
}

__global__ void scan_combine_kernel(const float* __restrict__ pa,
                                    const float* __restrict__ he,
                                    float* __restrict__ hin)
{
    const int idx = blockIdx.x * blockDim.x + threadIdx.x;
    if (idx >= BATCH * INNER * STATE) return;
    const int n = idx & 15;
    const int grp = idx >> 4;
    const int d = grp % INNER;
    const int b = grp / INNER;

    float h = 0.f;
    #pragma unroll
    for (int c = 0; c < CH; c++) {
        const size_t o = (((size_t)(b * CH + c) * INNER) + d) * STATE + n;
        hin[o] = h;
        h = pa[o] * h + he[o];
    }
}

__global__ void scan_fixup_kernel(const float* __restrict__ dsp_,
                                  const float* __restrict__ bc,
                                  const float* __restrict__ A_log,
                                  const float* __restrict__ hin,
                                  const float* __restrict__ yloc,
                                  const float* __restrict__ xz,
                                  float* __restrict__ y)
{
    const int idx = blockIdx.x * blockDim.x + threadIdx.x;
    const int n = idx & 15;
    const int grp = idx >> 4;
    const int d = grp % INNER;
    const int bch = grp / INNER;
    const int c = bch & (CH - 1);
    const int b = bch >> 4;

    const float A = -__expf(A_log[d * STATE + n]);
    const float h0 = hin[(size_t)grp * STATE + n];
    float S = 0.f;

    size_t tok = (size_t)b * SEQ + (size_t)c * CT;

    float dsp = dsp_[tok * INNER + d];
    float Cv  = bc[tok * 2 * STATE + STATE + n];

    for (int t = 0; t < CT; t++) {
        float dsp_nx = 0.f, c_nx = 0.f;
        if (t + 1 < CT) {
            const size_t tk = tok + 1;
            dsp_nx = dsp_[tk * INNER + d];
            c_nx   = bc[tk * 2 * STATE + STATE + n];
        }
        S += dsp;
        float p = Cv * __expf(A * S) * h0;
        p += __shfl_xor_sync(0xffffffffu, p, 8);
        p += __shfl_xor_sync(0xffffffffu, p, 4);
        p += __shfl_xor_sync(0xffffffffu, p, 2);
        p += __shfl_xor_sync(0xffffffffu, p, 1);
        if (n == 0) {
            const float zv = xz[tok * 2 * INNER + INNER + d];
            const float sz = zv / (1.f + __expf(-zv));
            y[tok * INNER + d] = tf32r((yloc[tok * INNER + d] + p) * sz);
        }
        tok++;
        dsp = dsp_nx; Cv = c_nx;
    }
}

// ---------------------------------------------------------------------------
// Fused: x2 = xres + LN(o); h2 = RMSNorm(x2)
// ---------------------------------------------------------------------------
__global__ void ln_residual_rms_kernel(const float* __restrict__ o_,
                                       const float* __restrict__ xres,
                                       const float* __restrict__ gamma,
                                       const float* __restrict__ beta,
                                       const float* __restrict__ rms_w,
                                       float* __restrict__ x2,
                                       float* __restrict__ h2)
{
    const int warp = (blockIdx.x * blockDim.x + threadIdx.x) >> 5;
    const int lane = threadIdx.x & 31;
    if (warp >= TOK) return;
    const size_t row = (size_t)warp * DMODEL;

    float o[12];
    float mu = 0.f;
    #pragma unroll
    for (int c = 0; c < 12; c++) {
        o[c] = o_[row + lane + c * 32];
        mu += o[c];
    }
    #pragma unroll
    for (int s = 16; s; s >>= 1) mu += __shfl_xor_sync(0xffffffffu, mu, s);
    mu *= (1.f / DMODEL);

    float var = 0.f;
    #pragma unroll
    for (int c = 0; c < 12; c++) {
        const float dd = o[c] - mu;
        var += dd * dd;
    }
    #pragma unroll
    for (int s = 16; s; s >>= 1) var += __shfl_xor_sync(0xffffffffu, var, s);
    var *= (1.f / DMODEL);
    const float inv = rsqrtf(var + 1e-5f);

    float r[12];
    float ss = 0.f;
    #pragma unroll
    for (int c = 0; c < 12; c++) {
        const int i = lane + c * 32;
        const float v = xres[row + i] + (o[c] - mu) * inv * gamma[i] + beta[i];
        r[c] = v;
        x2[row + i] = v;
        ss += v * v;
    }
    #pragma unroll
    for (int s = 16; s; s >>= 1) ss += __shfl_xor_sync(0xffffffffu, ss, s);
    const float rinv = rsqrtf(ss * (1.f / DMODEL) + 1e-6f);
    #pragma unroll
    for (int c = 0; c < 12; c++) {
        const int i = lane + c * 32;
        h2[row + i] = tf32r(r[c] * rinv * rms_w[i]);
    }
}

// ---------------------------------------------------------------------------
// launch — cross-stream fork/join so independent kernels overlap in the graph
// ---------------------------------------------------------------------------
static inline float* sym(const void* symbol)
{
    void* p = nullptr;
    cudaGetSymbolAddress(&p, symbol);
    return (float*)p;
}

extern "C" void kernel_launch(void* const* d_in, const int* in_sizes, int n_in,
                              void* d_out, int out_size)
{
    const float* x        = (const float*)d_in[0];
    const float* rms1_w   = (const float*)d_in[1];
    const float* rms2_w   = (const float*)d_in[2];
    const float* in_proj  = (const float*)d_in[3];
    const float* conv_w   = (const float*)d_in[4];
    const float* conv_b   = (const float*)d_in[5];
    const float* x_proj   = (const float*)d_in[6];
    const float* dt_proj  = (const float*)d_in[7];
    const float* dt_b     = (const float*)d_in[8];
    const float* A_log    = (const float*)d_in[9];
    const float* D_param  = (const float*)d_in[10];
    const float* out_proj = (const float*)d_in[11];
    const float* ln_g     = (const float*)d_in[12];
    const float* ln_b     = (const float*)d_in[13];
    const float* gate_w   = (const float*)d_in[14];
    const float* up_w     = (const float*)d_in[15];
    const float* down_w   = (const float*)d_in[16];
    float* out = (float*)d_out;

    float* h    = sym(g_h);
    float* xz   = sym(g_xz);
    float* xc   = sym(g_xc);
    float* bcp  = sym(g_bc);
    float* dl   = sym(g_dl);
    float* y    = sym(g_y);
    float* o    = sym(g_o);
    float* x2   = sym(g_x2);
    float* h2   = sym(g_h2);
    float* gate = sym(g_gate);
    float* hid  = sym(g_hid);
    float* pa   = sym(g_pa);
    float* he   = sym(g_he);
    float* hin  = sym(g_hin);
    float* wip  = sym(g_wip);
    float* wcv  = sym(g_wcv);
    float* wxp  = sym(g_wxp);
    float* wdt  = sym(g_wdt);
    float* wop  = sym(g_wop);
    float* wgt  = sym(g_wgt);
    float* wup  = sym(g_wup);
    float* wdn  = sym(g_wdn);

    // side stream + events, created once on the first (non-capture) call so
    // no creation APIs run during graph capture. Replay cost: zero — the
    // fork/join becomes graph-DAG edges.
    static cudaStream_t s2 = nullptr;
    static cudaEvent_t evFork1 = nullptr, evJoin1 = nullptr;
    static cudaEvent_t evFork2 = nullptr, evJoin2 = nullptr;
    if (s2 == nullptr) {
        cudaStreamCreateWithFlags(&s2, cudaStreamNonBlocking);
        cudaEventCreateWithFlags(&evFork1, cudaEventDisableTiming);
        cudaEventCreateWithFlags(&evJoin1, cudaEventDisableTiming);
        cudaEventCreateWithFlags(&evFork2, cudaEventDisableTiming);
        cudaEventCreateWithFlags(&evJoin2, cudaEventDisableTiming);
    }

    const dim3 tpb(256);
    cudaStream_t s0 = 0;   // legacy/default stream (the captured stream)

    // ── fork 1: prep_weights on s2  ∥  rmsnorm on s0 ────────────────────
    cudaEventRecord(evFork1, s0);
    cudaStreamWaitEvent(s2, evFork1, 0);
    prep_weights_kernel<<<(NTOTW + 255) / 256, tpb, 0, s2>>>(
        in_proj, conv_w, x_proj, dt_proj, out_proj, gate_w, up_w, down_w);
    cudaEventRecord(evJoin1, s2);

    rmsnorm_kernel<<<TOK / 8, 256, 0, s0>>>(x, rms1_w, h);

    cudaStreamWaitEvent(s0, evJoin1, 0);   // join before first weight use

    // 2. xz = h @ in_proj   N=1536 K=384
    mma_gemm_kernel<<<dim3(1536 / BN, TOK / BM), tpb, 0, s0>>>(
        h, wip, xz, TOK, 2 * INNER, DMODEL, 2 * INNER, 0, nullptr, nullptr, 0);

    // 3+4. xc = silu(conv(x_inner) + b) — im2col folded into cp.async A-path
    mma_gemm_kernel<<<dim3(INNER / BN, TOK / BM), tpb, 0, s0>>>(
        xz, wcv, xc, TOK, INNER, KW * INNER, INNER, 1, conv_b, nullptr, 1);

    // ── fork 2: x_proj GEMM on s2  ∥  dt_proj GEMM on s0 ────────────────
    cudaEventRecord(evFork2, s0);
    cudaStreamWaitEvent(s2, evFork2, 0);
    mma_gemm_kernel<<<dim3(NXPAD / BN, TOK / BM), tpb, 0, s2>>>(
        xc, wxp, bcp, TOK, NXPAD, INNER, 2 * STATE, 0, nullptr, nullptr, 0);
    cudaEventRecord(evJoin2, s2);

    mma_gemm_kernel<<<dim3(INNER / BN, TOK / BM), tpb, 0, s0>>>(
        xc, wdt, dl, TOK, INNER, INNER, INNER, 4, dt_b, nullptr, 0);

    cudaStreamWaitEvent(s0, evJoin2, 0);   // join before scan reads bc

    // 7. chunked scan + gating
    scan_chunk_kernel<<<(BATCH * CH * INNER * STATE) / 256, tpb, 0, s0>>>(
        xc, dl, bcp, A_log, D_param, y, pa, he);
    scan_combine_kernel<<<(BATCH * INNER * STATE + 255) / 256, tpb, 0, s0>>>(
        pa, he, hin);
    scan_fixup_kernel<<<(BATCH * CH * INNER * STATE) / 256, tpb, 0, s0>>>(
        dl, bcp, A_log, hin, y, xz, y);

    // 8. o = y @ out_proj   N=384 K=768
    mma_gemm_kernel<<<dim3(DMODEL / BN, TOK / BM), tpb, 0, s0>>>(
        y, wop, o, TOK, DMODEL, INNER, DMODEL, 0, nullptr, nullptr, 0);

    // 9. x2 = x + LN(o); h2 = RMSNorm(x2)
    ln_residual_rms_kernel<<<TOK / 8, 256, 0, s0>>>(
        o, x, ln_g, ln_b, rms2_w, x2, h2);

    // 10. gate = h2 @ gate_w   N=1024 K=384
    mma_gemm_kernel<<<dim3(FFN / BN, TOK / BM), tpb, 0, s0>>>(
        h2, wgt, gate, TOK, FFN, DMODEL, FFN, 0, nullptr, nullptr, 0);
    // 11. hid = silu(gate) * (h2 @ up_w)
    mma_gemm_kernel<<<dim3(FFN / BN, TOK / BM), tpb, 0, s0>>>(
        h2, wup, hid, TOK, FFN, DMODEL, FFN, 5, nullptr, gate, 0);

    // 12. out = x2 + hid @ down_w   N=384 K=1024  (exact, no rounding)
    mma_gemm_kernel<<<dim3(DMODEL / BN, TOK / BM), tpb, 0, s0>>>(
        hid, wdn, out, TOK, DMODEL, FFN, DMODEL, 3, nullptr, x2, 0);
}

// round 17
// speedup vs baseline: 1.1467x; 1.0261x over previous
#include <cuda_runtime.h>
#include <cuda_bf16.h>
#include <cstdint>
#include <cstddef>

// ---------------------------------------------------------------------------
// Problem dims (fixed)
// ---------------------------------------------------------------------------
#define BATCH   4
#define SEQ     2048
#define TOK     (BATCH * SEQ)      // 8192
#define DMODEL  384
#define INNER   768
#define STATE   16
#define KW      4
#define FFN     1024

// scan chunking
#define CH      16
#define CT      (SEQ / CH)         // 128

// padded x_proj width
#define NXPAD   128

// ---------------------------------------------------------------------------
// Scratch (device globals; no allocation allowed)
// ---------------------------------------------------------------------------
__device__ float g_h   [TOK * DMODEL];
__device__ float g_xz  [TOK * 2 * INNER];
__device__ float g_xc  [TOK * INNER];
__device__ float g_bc  [TOK * 2 * STATE];
__device__ float g_dl  [TOK * INNER];
__device__ float g_y   [TOK * INNER];
__device__ float g_x2  [TOK * DMODEL];
__device__ float g_h2  [TOK * DMODEL];
__device__ float g_gate[TOK * FFN];
__device__ float g_hid [TOK * FFN];
__device__ float g_part[2 * TOK * INNER];    // split-K partials (largest use)
__device__ float g_pa  [BATCH * CH * INNER * STATE];
__device__ float g_he  [BATCH * CH * INNER * STATE];
__device__ float g_hin [BATCH * CH * INNER * STATE];

// tf32-pre-rounded weights
__device__ float g_wip [DMODEL * 2 * INNER];
__device__ float g_wcv [KW * INNER * INNER];
__device__ float g_wxp [INNER * NXPAD];
__device__ float g_wdt [INNER * INNER];
__device__ float g_wop [INNER * DMODEL];
__device__ float g_wgt [DMODEL * FFN];
__device__ float g_wup [DMODEL * FFN];
__device__ float g_wdn [FFN * DMODEL];

// ---------------------------------------------------------------------------
// helpers
// ---------------------------------------------------------------------------
__device__ __forceinline__ float tf32r(float f)
{
    uint32_t u;
    asm("cvt.rna.tf32.f32 %0, %1;" : "=r"(u) : "f"(f));
    return __uint_as_float(u);
}

__device__ __forceinline__ void mma_tf32(float c[4], const uint32_t a[4],
                                         const uint32_t b[2])
{
    asm volatile(
        "mma.sync.aligned.m16n8k8.row.col.f32.tf32.tf32.f32 "
        "{%0,%1,%2,%3}, {%4,%5,%6,%7}, {%8,%9}, {%0,%1,%2,%3};\n"
        : "+f"(c[0]), "+f"(c[1]), "+f"(c[2]), "+f"(c[3])
        : "r"(a[0]), "r"(a[1]), "r"(a[2]), "r"(a[3]),
          "r"(b[0]), "r"(b[1]));
}

#define CP16(dst, src) \
    asm volatile("cp.async.cg.shared.global [%0], [%1], 16;\n" \
                 :: "r"(dst), "l"(src))
#define CP16Z(dst, src, sz) \
    asm volatile("cp.async.cg.shared.global [%0], [%1], 16, %2;\n" \
                 :: "r"(dst), "l"(src), "r"(sz))
#define CPCOMMIT() asm volatile("cp.async.commit_group;\n")
#define CPWAIT2()  asm volatile("cp.async.wait_group 2;\n")

// ---------------------------------------------------------------------------
// TF32 GEMM, cp.async 4-stage pipeline. All operands pre-rounded to tf32.
// Bs row stride 136 (mod 32 = 8) -> conflict-free B-fragment LDS.
// Split-K: blockIdx.z selects K-half; kbase = z*K; C += z*zstride.
// K = per-z depth (loop count), Ktot = A row stride (full K).
// mode: 0 store, 1 silu(acc+bias), 2 acc+bias, 3 acc+res (NO rounding),
//       4 softplus(acc+bias), 5 silu(res)*acc, 6 raw partial (NO rounding).
// Modes other than 3/6 round the stored value to tf32.
// amode: 0 dense A [M,Ktot]; 1 conv im2col view of xz (row stride 1536),
//        tap math uses global k = kbase + tile_k.
// ---------------------------------------------------------------------------
#define BM 128
#define BN 128
#define BKT 16
#define STG 4
#define BSTRIDE 136

__global__ __launch_bounds__(256, 2) void mma_gemm_kernel(
    const float* __restrict__ A, const float* __restrict__ B,
    float* __restrict__ C, int M, int N, int K, int Ktot, int Nc,
    long long zstride,
    int mode, const float* __restrict__ bias, const float* __restrict__ res,
    int amode)
{
    __shared__ float As[STG][128][20];
    __shared__ float Bs[STG][16][BSTRIDE];

    const int tid  = threadIdx.x;
    const int wid  = tid >> 5;
    const int lane = tid & 31;
    const int g    = lane >> 2;
    const int tig  = lane & 3;

    const int warpM = (wid & 3) * 32;
    const int warpN = (wid >> 2) * 64;

    const int m0 = blockIdx.y * BM;
    const int n0 = blockIdx.x * BN;
    const int kbase = blockIdx.z * K;

    C += (size_t)blockIdx.z * zstride;

    const int ar  = tid >> 2;         // 0..63
    const int ac  = (tid & 3) * 4;    // 0,4,8,12
    const int br  = tid >> 5;         // 0..7
    const int bcn = (tid & 31) * 4;   // 0..124

    const int arow0 = m0 + ar;                 // rows arow0, arow0+64
    const float* a0p = A + (size_t)arow0 * Ktot + kbase + ac;
    const float* a1p = A + (size_t)(arow0 + 64) * Ktot + kbase + ac;
    const float* b0p = B + (size_t)(kbase + br) * N + n0 + bcn;
    const float* b1p = B + (size_t)(kbase + br + 8) * N + n0 + bcn;

    uint32_t sa0[STG], sa1[STG], sb0[STG], sb1[STG];
    #pragma unroll
    for (int s = 0; s < STG; s++) {
        sa0[s] = (uint32_t)__cvta_generic_to_shared(&As[s][ar][ac]);
        sa1[s] = (uint32_t)__cvta_generic_to_shared(&As[s][ar + 64][ac]);
        sb0[s] = (uint32_t)__cvta_generic_to_shared(&Bs[s][br][bcn]);
        sb1[s] = (uint32_t)__cvta_generic_to_shared(&Bs[s][br + 8][bcn]);
    }

    // issue one tile's cp.asyncs into stage s
    auto issue = [&](int tn, int s) {
        if (amode == 0) {
            CP16(sa0[s], a0p + tn * 16);
            CP16(sa1[s], a1p + tn * 16);
        } else {
            const int k = kbase + tn * 16 + ac;
            const int w = (k >= INNER) + (k >= 2 * INNER) + (k >= 3 * INNER);
            const int i = k - w * INNER;
            const int bbase = arow0 & ~(SEQ - 1);
            const int ts0 = (arow0 & (SEQ - 1)) - 1 + w;
            const int ts1 = ts0 + 64;
            const int cl0 = ts0 < 0 ? 0 : (ts0 > SEQ - 1 ? SEQ - 1 : ts0);
            const int cl1 = ts1 > SEQ - 1 ? SEQ - 1 : ts1;
            const unsigned ok0 = ((unsigned)ts0 < SEQ) ? 16u : 0u;
            const unsigned ok1 = ((unsigned)ts1 < SEQ) ? 16u : 0u;
            CP16Z(sa0[s], A + (size_t)(bbase + cl0) * (2 * INNER) + i, ok0);
            CP16Z(sa1[s], A + (size_t)(bbase + cl1) * (2 * INNER) + i, ok1);
        }
        CP16(sb0[s], b0p + (size_t)(tn * 16) * N);
        CP16(sb1[s], b1p + (size_t)(tn * 16) * N);
    };

    float acc[2][8][4];
    #pragma unroll
    for (int mt = 0; mt < 2; mt++)
        #pragma unroll
        for (int nt = 0; nt < 8; nt++)
            #pragma unroll
            for (int r = 0; r < 4; r++) acc[mt][nt][r] = 0.f;

    const int ntiles = K / BKT;

    // prologue: tiles 0..2 -> stages 0..2
    #pragma unroll
    for (int s = 0; s < 3; s++) {
        issue(s, s);
        CPCOMMIT();
    }

    for (int t = 0; t < ntiles; t++) {
        CPWAIT2();
        __syncthreads();

        const int tn = t + 3;
        if (tn < ntiles)
            issue(tn, tn & 3);
        CPCOMMIT();

        const int st = t & 3;
        #pragma unroll
        for (int ks = 0; ks < BKT; ks += 8) {
            uint32_t afr[2][4];
            #pragma unroll
            for (int mt = 0; mt < 2; mt++) {
                const int mb = warpM + mt * 16 + g;
                afr[mt][0] = __float_as_uint(As[st][mb    ][ks + tig]);
                afr[mt][1] = __float_as_uint(As[st][mb + 8][ks + tig]);
                afr[mt][2] = __float_as_uint(As[st][mb    ][ks + tig + 4]);
                afr[mt][3] = __float_as_uint(As[st][mb + 8][ks + tig + 4]);
            }
            uint32_t bfr[8][2];
            #pragma unroll
            for (int nt = 0; nt < 8; nt++) {
                const int nb = warpN + nt * 8 + g;
                bfr[nt][0] = __float_as_uint(Bs[st][ks + tig    ][nb]);
                bfr[nt][1] = __float_as_uint(Bs[st][ks + tig + 4][nb]);
            }
            #pragma unroll
            for (int mt = 0; mt < 2; mt++)
                #pragma unroll
                for (int nt = 0; nt < 8; nt++)
                    mma_tf32(acc[mt][nt], afr[mt], bfr[nt]);
        }
    }

    // epilogue
    #pragma unroll
    for (int mt = 0; mt < 2; mt++) {
        #pragma unroll
        for (int nt = 0; nt < 8; nt++) {
            const int mA = m0 + warpM + mt * 16 + g;
            const int n  = n0 + warpN + nt * 8 + tig * 2;
            #pragma unroll
            for (int half = 0; half < 2; half++) {
                const int m = half ? (mA + 8) : mA;
                float v0 = half ? acc[mt][nt][2] : acc[mt][nt][0];
                float v1 = half ? acc[mt][nt][3] : acc[mt][nt][1];
                #pragma unroll
                for (int e = 0; e < 2; e++) {
                    const int nn = n + e;
                    float v = e ? v1 : v0;
                    if (nn >= Nc) continue;
                    if (mode == 1) {
                        v += bias[nn];
                        v = v / (1.f + __expf(-v));
                    } else if (mode == 2) {
                        v += bias[nn];
                    } else if (mode == 3) {
                        v += res[(size_t)m * Nc + nn];
                    } else if (mode == 4) {
                        v += bias[nn];
                        v = (v > 20.f) ? v : log1pf(__expf(v));
                    } else if (mode == 5) {
                        const float gv = res[(size_t)m * Nc + nn];
                        v *= gv / (1.f + __expf(-gv));
                    }
                    if (mode != 3 && mode != 6) v = tf32r(v);
                    C[(size_t)m * Nc + nn] = v;
                }
            }
        }
    }
}

// ---------------------------------------------------------------------------
// Pre-round all weights into device globals (single launch).
// x_proj is padded 32 -> 128 columns with zeros.
// ---------------------------------------------------------------------------
#define NIP (DMODEL * 2 * INNER)
#define NCV (KW * INNER * INNER)
#define NXP (INNER * NXPAD)
#define NDT (INNER * INNER)
#define NOP (INNER * DMODEL)
#define NGT (DMODEL * FFN)
#define NTOTW (NIP + NCV + NXP + NDT + NOP + 3 * NGT)

__global__ void prep_weights_kernel(const float* __restrict__ ip,
                                    const float* __restrict__ cv,
                                    const float* __restrict__ xp,
                                    const float* __restrict__ dt,
                                    const float* __restrict__ op,
                                    const float* __restrict__ gt,
                                    const float* __restrict__ up,
                                    const float* __restrict__ dn)
{
    int i = blockIdx.x * blockDim.x + threadIdx.x;
    if (i >= NTOTW) return;
    if (i < NIP) { g_wip[i] = tf32r(ip[i]); return; }
    i -= NIP;
    if (i < NCV) { g_wcv[i] = tf32r(cv[i]); return; }
    i -= NCV;
    if (i < NXP) {
        const int k = i >> 7, n = i & (NXPAD - 1);
        g_wxp[i] = (n < 2 * STATE) ? tf32r(xp[k * 2 * STATE + n]) : 0.f;
        return;
    }
    i -= NXP;
    if (i < NDT) { g_wdt[i] = tf32r(dt[i]); return; }
    i -= NDT;
    if (i < NOP) { g_wop[i] = tf32r(op[i]); return; }
    i -= NOP;
    if (i < NGT) { g_wgt[i] = tf32r(gt[i]); return; }
    i -= NGT;
    if (i < NGT) { g_wup[i] = tf32r(up[i]); return; }
    i -= NGT;
    g_wdn[i] = tf32r(dn[i]);
}

// ---------------------------------------------------------------------------
// conv combine: xc = tf32r(silu(p0 + p1 + bias))   (float4 grain)
// ---------------------------------------------------------------------------
__global__ void conv_combine_kernel(const float* __restrict__ p0,
                                    const float* __restrict__ p1,
                                    const float* __restrict__ bias,
                                    float* __restrict__ xc)
{
    const int idx = blockIdx.x * blockDim.x + threadIdx.x;
    if (idx >= TOK * INNER / 4) return;
    const int e = idx * 4;
    const int n = e % INNER;
    const float4 a = *(const float4*)(p0 + e);
    const float4 b = *(const float4*)(p1 + e);
    const float4 bb = *(const float4*)(bias + n);
    float4 r;
    float v;
    v = a.x + b.x + bb.x; r.x = tf32r(v / (1.f + __expf(-v)));
    v = a.y + b.y + bb.y; r.y = tf32r(v / (1.f + __expf(-v)));
    v = a.z + b.z + bb.z; r.z = tf32r(v / (1.f + __expf(-v)));
    v = a.w + b.w + bb.w; r.w = tf32r(v / (1.f + __expf(-v)));
    *(float4*)(xc + e) = r;
}

// ---------------------------------------------------------------------------
// final add: out = x2 + d0 + d1   (float4 grain)
// ---------------------------------------------------------------------------
__global__ void final_add_kernel(const float* __restrict__ x2,
                                 const float* __restrict__ d0,
                                 const float* __restrict__ d1,
                                 float* __restrict__ out)
{
    const int idx = blockIdx.x * blockDim.x + threadIdx.x;
    if (idx >= TOK * DMODEL / 4) return;
    const int e = idx * 4;
    const float4 a = *(const float4*)(x2 + e);
    const float4 b = *(const float4*)(d0 + e);
    const float4 c = *(const float4*)(d1 + e);
    float4 r;
    r.x = a.x + b.x + c.x;
    r.y = a.y + b.y + c.y;
    r.z = a.z + b.z + c.z;
    r.w = a.w + b.w + c.w;
    *(float4*)(out + e) = r;
}

// ---------------------------------------------------------------------------
// RMSNorm (warp per token) — output tf32-rounded
// ---------------------------------------------------------------------------
__global__ void rmsnorm_kernel(const float* __restrict__ x,
                               const float* __restrict__ w,
                               float* __restrict__ out)
{
    const int warp = (blockIdx.x * blockDim.x + threadIdx.x) >> 5;
    const int lane = threadIdx.x & 31;
    if (warp >= TOK) return;
    const float* row = x + (size_t)warp * DMODEL;
    float ss = 0.f;
    float v[12];
    #pragma unroll
    for (int c = 0; c < 12; c++) {
        v[c] = row[lane + c * 32];
        ss += v[c] * v[c];
    }
    #pragma unroll
    for (int o = 16; o; o >>= 1) ss += __shfl_xor_sync(0xffffffffu, ss, o);
    const float inv = rsqrtf(ss * (1.f / DMODEL) + 1e-6f);
    float* orow = out + (size_t)warp * DMODEL;
    #pragma unroll
    for (int c = 0; c < 12; c++) {
        const int i = lane + c * 32;
        orow[i] = tf32r(v[c] * inv * w[i]);
    }
}

// ---------------------------------------------------------------------------
// Chunked selective scan
// ---------------------------------------------------------------------------
__global__ void scan_chunk_kernel(const float* __restrict__ xc,
                                  const float* __restrict__ dsp_,
                                  const float* __restrict__ bc,
                                  const float* __restrict__ A_log,
                                  const float* __restrict__ Dp,
                                  float* __restrict__ yloc,
                                  float* __restrict__ pa,
                                  float* __restrict__ he)
{
    const int idx = blockIdx.x * blockDim.x + threadIdx.x;
    const int n = idx & 15;
    const int grp = idx >> 4;
    const int d = grp % INNER;
    const int bch = grp / INNER;
    const int c = bch & (CH - 1);
    const int b = bch >> 4;

    const float A = -__expf(A_log[d * STATE + n]);
    const float Dv = Dp[d];
    float S = 0.f, s = 0.f;

    size_t tok = (size_t)b * SEQ + (size_t)c * CT;

    float dsp = dsp_[tok * INNER + d];
    float xv  = xc[tok * INNER + d];
    float Bv  = bc[tok * 2 * STATE + n];
    float Cv  = bc[tok * 2 * STATE + STATE + n];

    for (int t = 0; t < CT; t++) {
        float dsp_nx = 0.f, x_nx = 0.f, b_nx = 0.f, c_nx = 0.f;
        if (t + 1 < CT) {
            const size_t tk = tok + 1;
            dsp_nx = dsp_[tk * INNER + d];
            x_nx   = xc[tk * INNER + d];
            b_nx   = bc[tk * 2 * STATE + n];
            c_nx   = bc[tk * 2 * STATE + STATE + n];
        }
        S += dsp;
        const float a = __expf(A * dsp);
        s = a * s + dsp * Bv * xv;
        float p = Cv * s;
        p += __shfl_xor_sync(0xffffffffu, p, 8);
        p += __shfl_xor_sync(0xffffffffu, p, 4);
        p += __shfl_xor_sync(0xffffffffu, p, 2);
        p += __shfl_xor_sync(0xffffffffu, p, 1);
        if (n == 0)
            yloc[tok * INNER + d] = p + Dv * xv;
        tok++;
        dsp = dsp_nx; xv = x_nx; Bv = b_nx; Cv = c_nx;
    }

    const size_t o = (size_t)grp * STATE + n;
    pa[o] = __expf(A * S);
    he[o] = s;
}

__global__ void scan_combine_kernel(const float* __restrict__ pa,
                                    const float* __restrict__ he,
                                    float* __restrict__ hin)
{
    const int idx = blockIdx.x * blockDim.x + threadIdx.x;
    if (idx >= BATCH * INNER * STATE) return;
    const int n = idx & 15;
    const int grp = idx >> 4;
    const int d = grp % INNER;
    const int b = grp / INNER;

    float h = 0.f;
    #pragma unroll
    for (int c = 0; c < CH; c++) {
        const size_t o = (((size_t)(b * CH + c) * INNER) + d) * STATE + n;
        hin[o] = h;
        h = pa[o] * h + he[o];
    }
}

__global__ void scan_fixup_kernel(const float* __restrict__ dsp_,
                                  const float* __restrict__ bc,
                                  const float* __restrict__ A_log,
                                  const float* __restrict__ hin,
                                  const float* __restrict__ yloc,
                                  const float* __restrict__ xz,
                                  float* __restrict__ y)
{
    const int idx = blockIdx.x * blockDim.x + threadIdx.x;
    const int n = idx & 15;
    const int grp = idx >> 4;
    const int d = grp % INNER;
    const int bch = grp / INNER;
    const int c = bch & (CH - 1);
    const int b = bch >> 4;

    const float A = -__expf(A_log[d * STATE + n]);
    const float h0 = hin[(size_t)grp * STATE + n];
    float S = 0.f;

    size_t tok = (size_t)b * SEQ + (size_t)c * CT;

    float dsp = dsp_[tok * INNER + d];
    float Cv  = bc[tok * 2 * STATE + STATE + n];

    for (int t = 0; t < CT; t++) {
        float dsp_nx = 0.f, c_nx = 0.f;
        if (t + 1 < CT) {
            const size_t tk = tok + 1;
            dsp_nx = dsp_[tk * INNER + d];
            c_nx   = bc[tk * 2 * STATE + STATE + n];
        }
        S += dsp;
        float p = Cv * __expf(A * S) * h0;
        p += __shfl_xor_sync(0xffffffffu, p, 8);
        p += __shfl_xor_sync(0xffffffffu, p, 4);
        p += __shfl_xor_sync(0xffffffffu, p, 2);
        p += __shfl_xor_sync(0xffffffffu, p, 1);
        if (n == 0) {
            const float zv = xz[tok * 2 * INNER + INNER + d];
            const float sz = zv / (1.f + __expf(-zv));
            y[tok * INNER + d] = tf32r((yloc[tok * INNER + d] + p) * sz);
        }
        tok++;
        dsp = dsp_nx; Cv = c_nx;
    }
}

// ---------------------------------------------------------------------------
// Fused: x2 = xres + LN(o0+o1); h2 = RMSNorm(x2)
// ---------------------------------------------------------------------------
__global__ void ln_residual_rms_kernel(const float* __restrict__ o0,
                                       const float* __restrict__ o1,
                                       const float* __restrict__ xres,
                                       const float* __restrict__ gamma,
                                       const float* __restrict__ beta,
                                       const float* __restrict__ rms_w,
                                       float* __restrict__ x2,
                                       float* __restrict__ h2)
{
    const int warp = (blockIdx.x * blockDim.x + threadIdx.x) >> 5;
    const int lane = threadIdx.x & 31;
    if (warp >= TOK) return;
    const size_t row = (size_t)warp * DMODEL;

    float o[12];
    float mu = 0.f;
    #pragma unroll
    for (int c = 0; c < 12; c++) {
        const size_t i = row + lane + c * 32;
        o[c] = o0[i] + o1[i];
        mu += o[c];
    }
    #pragma unroll
    for (int s = 16; s; s >>= 1) mu += __shfl_xor_sync(0xffffffffu, mu, s);
    mu *= (1.f / DMODEL);

    float var = 0.f;
    #pragma unroll
    for (int c = 0; c < 12; c++) {
        const float dd = o[c] - mu;
        var += dd * dd;
    }
    #pragma unroll
    for (int s = 16; s; s >>= 1) var += __shfl_xor_sync(0xffffffffu, var, s);
    var *= (1.f / DMODEL);
    const float inv = rsqrtf(var + 1e-5f);

    float r[12];
    float ss = 0.f;
    #pragma unroll
    for (int c = 0; c < 12; c++) {
        const int i = lane + c * 32;
        const float v = xres[row + i] + (o[c] - mu) * inv * gamma[i] + beta[i];
        r[c] = v;
        x2[row + i] = v;
        ss += v * v;
    }
    #pragma unroll
    for (int s = 16; s; s >>= 1) ss += __shfl_xor_sync(0xffffffffu, ss, s);
    const float rinv = rsqrtf(ss * (1.f / DMODEL) + 1e-6f);
    #pragma unroll
    for (int c = 0; c < 12; c++) {
        const int i = lane + c * 32;
        h2[row + i] = tf32r(r[c] * rinv * rms_w[i]);
    }
}

// ---------------------------------------------------------------------------
// launch — cross-stream fork/join + split-K GEMMs
// ---------------------------------------------------------------------------
static inline float* sym(const void* symbol)
{
    void* p = nullptr;
    cudaGetSymbolAddress(&p, symbol);
    return (float*)p;
}

extern "C" void kernel_launch(void* const* d_in, const int* in_sizes, int n_in,
                              void* d_out, int out_size)
{
    const float* x        = (const float*)d_in[0];
    const float* rms1_w   = (const float*)d_in[1];
    const float* rms2_w   = (const float*)d_in[2];
    const float* in_proj  = (const float*)d_in[3];
    const float* conv_w   = (const float*)d_in[4];
    const float* conv_b   = (const float*)d_in[5];
    const float* x_proj   = (const float*)d_in[6];
    const float* dt_proj  = (const float*)d_in[7];
    const float* dt_b     = (const float*)d_in[8];
    const float* A_log    = (const float*)d_in[9];
    const float* D_param  = (const float*)d_in[10];
    const float* out_proj = (const float*)d_in[11];
    const float* ln_g     = (const float*)d_in[12];
    const float* ln_b     = (const float*)d_in[13];
    const float* gate_w   = (const float*)d_in[14];
    const float* up_w     = (const float*)d_in[15];
    const float* down_w   = (const float*)d_in[16];
    float* out = (float*)d_out;

    float* h    = sym(g_h);
    float* xz   = sym(g_xz);
    float* xc   = sym(g_xc);
    float* bcp  = sym(g_bc);
    float* dl   = sym(g_dl);
    float* y    = sym(g_y);
    float* x2   = sym(g_x2);
    float* h2   = sym(g_h2);
    float* gate = sym(g_gate);
    float* hid  = sym(g_hid);
    float* part = sym(g_part);
    float* pa   = sym(g_pa);
    float* he   = sym(g_he);
    float* hin  = sym(g_hin);
    float* wip  = sym(g_wip);
    float* wcv  = sym(g_wcv);
    float* wxp  = sym(g_wxp);
    float* wdt  = sym(g_wdt);
    float* wop  = sym(g_wop);
    float* wgt  = sym(g_wgt);
    float* wup  = sym(g_wup);
    float* wdn  = sym(g_wdn);

    static cudaStream_t s2 = nullptr;
    static cudaEvent_t evFork1 = nullptr, evJoin1 = nullptr;
    static cudaEvent_t evFork2 = nullptr, evJoin2 = nullptr;
    if (s2 == nullptr) {
        cudaStreamCreateWithFlags(&s2, cudaStreamNonBlocking);
        cudaEventCreateWithFlags(&evFork1, cudaEventDisableTiming);
        cudaEventCreateWithFlags(&evJoin1, cudaEventDisableTiming);
        cudaEventCreateWithFlags(&evFork2, cudaEventDisableTiming);
        cudaEventCreateWithFlags(&evJoin2, cudaEventDisableTiming);
    }

    const dim3 tpb(256);
    cudaStream_t s0 = 0;

    // ── fork 1: prep_weights on s2  ∥  rmsnorm on s0 ────────────────────
    cudaEventRecord(evFork1, s0);
    cudaStreamWaitEvent(s2, evFork1, 0);
    prep_weights_kernel<<<(NTOTW + 255) / 256, tpb, 0, s2>>>(
        in_proj, conv_w, x_proj, dt_proj, out_proj, gate_w, up_w, down_w);
    cudaEventRecord(evJoin1, s2);

    rmsnorm_kernel<<<TOK / 8, 256, 0, s0>>>(x, rms1_w, h);

    cudaStreamWaitEvent(s0, evJoin1, 0);

    // 2. xz = h @ in_proj   N=1536 K=384
    mma_gemm_kernel<<<dim3(1536 / BN, TOK / BM), tpb, 0, s0>>>(
        h, wip, xz, TOK, 2 * INNER, DMODEL, DMODEL, 2 * INNER, 0,
        0, nullptr, nullptr, 0);

    // 3. conv split-K=2 (raw partials) — im2col folded, K=1536 per z
    mma_gemm_kernel<<<dim3(INNER / BN, TOK / BM, 2), tpb, 0, s0>>>(
        xz, wcv, part, TOK, INNER, (KW * INNER) / 2, KW * INNER, INNER,
        (long long)TOK * INNER, 6, nullptr, nullptr, 1);

    // 4. xc = tf32r(silu(p0 + p1 + conv_b))
    conv_combine_kernel<<<(TOK * INNER / 4 + 255) / 256, tpb, 0, s0>>>(
        part, part + (size_t)TOK * INNER, conv_b, xc);

    // ── fork 2: x_proj GEMM on s2  ∥  dt_proj GEMM on s0 ────────────────
    cudaEventRecord(evFork2, s0);
    cudaStreamWaitEvent(s2, evFork2, 0);
    mma_gemm_kernel<<<dim3(NXPAD / BN, TOK / BM), tpb, 0, s2>>>(
        xc, wxp, bcp, TOK, NXPAD, INNER, INNER, 2 * STATE, 0,
        0, nullptr, nullptr, 0);
    cudaEventRecord(evJoin2, s2);

    mma_gemm_kernel<<<dim3(INNER / BN, TOK / BM), tpb, 0, s0>>>(
        xc, wdt, dl, TOK, INNER, INNER, INNER, INNER, 0,
        4, dt_b, nullptr, 0);

    cudaStreamWaitEvent(s0, evJoin2, 0);

    // 7. chunked scan + gating
    scan_chunk_kernel<<<(BATCH * CH * INNER * STATE) / 256, tpb, 0, s0>>>(
        xc, dl, bcp, A_log, D_param, y, pa, he);
    scan_combine_kernel<<<(BATCH * INNER * STATE + 255) / 256, tpb, 0, s0>>>(
        pa, he, hin);
    scan_fixup_kernel<<<(BATCH * CH * INNER * STATE) / 256, tpb, 0, s0>>>(
        dl, bcp, A_log, hin, y, xz, y);

    // 8. out_proj split-K=2 (raw partials)  N=384, K=384 per z
    mma_gemm_kernel<<<dim3(DMODEL / BN, TOK / BM, 2), tpb, 0, s0>>>(
        y, wop, part, TOK, DMODEL, INNER / 2, INNER, DMODEL,
        (long long)TOK * DMODEL, 6, nullptr, nullptr, 0);

    // 9. x2 = x + LN(o0+o1); h2 = RMSNorm(x2)
    ln_residual_rms_kernel<<<TOK / 8, 256, 0, s0>>>(
        part, part + (size_t)TOK * DMODEL, x, ln_g, ln_b, rms2_w, x2, h2);

    // 10. gate = h2 @ gate_w   N=1024 K=384
    mma_gemm_kernel<<<dim3(FFN / BN, TOK / BM), tpb, 0, s0>>>(
        h2, wgt, gate, TOK, FFN, DMODEL, DMODEL, FFN, 0,
        0, nullptr, nullptr, 0);
    // 11. hid = silu(gate) * (h2 @ up_w)
    mma_gemm_kernel<<<dim3(FFN / BN, TOK / BM), tpb, 0, s0>>>(
        h2, wup, hid, TOK, FFN, DMODEL, DMODEL, FFN, 0,
        5, nullptr, gate, 0);

    // 12. down split-K=2 (raw partials)  N=384, K=512 per z
    mma_gemm_kernel<<<dim3(DMODEL / BN, TOK / BM, 2), tpb, 0, s0>>>(
        hid, wdn, part, TOK, DMODEL, FFN / 2, FFN, DMODEL,
        (long long)TOK * DMODEL, 6, nullptr, nullptr, 0);

    // 13. out = x2 + d0 + d1
    final_add_kernel<<<(TOK * DMODEL / 4 + 255) / 256, tpb, 0, s0>>>(
        x2, part, part + (size_t)TOK * DMODEL, out);
}